// round 6
// baseline (speedup 1.0000x reference)
#include <cuda_runtime.h>
#include <stdint.h>
#include <math.h>

constexpr int Bn   = 4;
constexpr int Tn   = 480000;
constexpr int DIMn = 9;
constexpr int CHUNK = 512;
constexpr int TPB   = 128;
constexpr int SPT   = CHUNK / TPB;               // 4
constexpr int NCH   = (Tn + CHUNK - 1) / CHUNK;  // 938

constexpr float LO_NORMAL = -0.99999994f;
constexpr float SQRT2F    = 1.41421356237309504880f;
constexpr float RCP48K    = 2.08333333333333333e-05f;  // fl(1/48000)

constexpr int WPS  = SPT * DIMn;      // 36 words per thread
constexpr int WPSP = WPS + 1;         // padded stride 37

struct RandIniFx { unsigned long long v[Bn * DIMn]; };
struct NKey      { uint32_t k0, k1; };

// ---- decoupled-lookback state (reset by k_clear every launch) ----
__device__ unsigned long long g_agg [Bn * NCH][DIMn];  // chunk aggregate
__device__ unsigned long long g_pref[Bn * NCH][DIMn];  // inclusive prefix
__device__ unsigned int       g_flag[Bn * NCH];        // 0=none 1=agg 2=prefix

// ---------------- threefry2x32-20 ----------------
__host__ __device__ __forceinline__ uint32_t rotl32(uint32_t x, int r) {
#ifdef __CUDA_ARCH__
  return __funnelshift_l(x, x, r);
#else
  return (x << r) | (x >> (32 - r));
#endif
}

__host__ __device__ __forceinline__ void tf2x32(uint32_t k0, uint32_t k1,
                                                uint32_t x0, uint32_t x1,
                                                uint32_t& o0, uint32_t& o1) {
  uint32_t k2 = k0 ^ k1 ^ 0x1BD11BDAu;
#define TFR(r) { x0 += x1; x1 = rotl32(x1, (r)); x1 ^= x0; }
  x0 += k0; x1 += k1;
  TFR(13) TFR(15) TFR(26) TFR(6)
  x0 += k1; x1 += k2 + 1u;
  TFR(17) TFR(29) TFR(16) TFR(24)
  x0 += k2; x1 += k0 + 2u;
  TFR(13) TFR(15) TFR(26) TFR(6)
  x0 += k0; x1 += k1 + 3u;
  TFR(17) TFR(29) TFR(16) TFR(24)
  x0 += k1; x1 += k2 + 4u;
  TFR(13) TFR(15) TFR(26) TFR(6)
  x0 += k2; x1 += k0 + 5u;
#undef TFR
  o0 = x0; o1 = x1;
}

__host__ __device__ __forceinline__ uint32_t rng_bits(uint32_t k0, uint32_t k1,
                                                      uint32_t idx) {
  uint32_t a, b;
  tf2x32(k0, k1, 0u, idx, a, b);
  return a ^ b;
}

__host__ __device__ __forceinline__ float bits01(uint32_t bits) {
  union { uint32_t u; float f; } c;
  c.u = (bits >> 9) | 0x3F800000u;
  return c.f - 1.0f;
}

// ---------------- XLA ErfInv32 (fast log; noise error budget ~1e-2) --------
__device__ __forceinline__ float erfinv_xla(float x) {
  float w = -__logf(fmaf(-x, x, 1.0f));
  float p;
  if (w < 5.0f) {
    w = w - 2.5f;
    p =             2.81022636e-08f;
    p = fmaf(p, w,  3.43273939e-07f);
    p = fmaf(p, w, -3.5233877e-06f);
    p = fmaf(p, w, -4.39150654e-06f);
    p = fmaf(p, w,  0.00021858087f);
    p = fmaf(p, w, -0.00125372503f);
    p = fmaf(p, w, -0.00417768164f);
    p = fmaf(p, w,  0.246640727f);
    p = fmaf(p, w,  1.50140941f);
  } else {
    w = sqrtf(w) - 3.0f;
    p =            -0.000200214257f;
    p = fmaf(p, w,  0.000100950558f);
    p = fmaf(p, w,  0.00134934322f);
    p = fmaf(p, w, -0.00367342844f);
    p = fmaf(p, w,  0.00573950773f);
    p = fmaf(p, w, -0.0076224613f);
    p = fmaf(p, w,  0.00943887047f);
    p = fmaf(p, w,  1.00167406f);
    p = fmaf(p, w,  2.83297682f);
  }
  return p * x;
}

// correctly-rounded x/48000 via Markstein (bit-identical to __fdiv_rn)
__device__ __forceinline__ float div48k(float x) {
  float q0 = __fmul_rn(x, RCP48K);
  float e  = fmaf(-48000.0f, q0, x);
  return fmaf(e, RCP48K, q0);
}

// rad in u32 fixed point (2^-33 turns) — exact
__device__ __forceinline__ uint32_t rad_fx(float f0v, int h) {
  float rad = div48k(__fmul_rn(f0v, (float)(h + 1)));
  return (uint32_t)(rad * 8589934592.0f);   // rad * 2^33
}

// sin(2*pi*frac) * 0.1 from u32 phase (2^-32 turns). No MUFU.
__device__ __forceinline__ float sine_from_p32(uint32_t p32) {
  bool refl = (int32_t)(p32 + 0x40000000u) < 0;
  int32_t yi = refl ? (int32_t)(0x80000000u - p32) : (int32_t)p32;
  float x  = (float)yi * 4.65661287307739258e-10f;   // -> [-0.5, 0.5]
  float x2 = x * x;
  float p =            0.0821458866f;     // deg-9 odd poly for sin(pi x)
  p = fmaf(p, x2, -0.599264529f);
  p = fmaf(p, x2,  2.55016404f);
  p = fmaf(p, x2, -5.16771278f);
  p = fmaf(p, x2,  3.14159265f);
  return (x * 0.1f) * p;
}

// ---------------- K0: clear lookback flags (every launch, replay-safe) -----
__global__ void k_clear() {
  int i = blockIdx.x * blockDim.x + threadIdx.x;
  if (i < Bn * NCH) g_flag[i] = 0u;
}

// ---------------- K: fused single-pass scan + emit --------------------------
__global__ void __launch_bounds__(TPB) k_fused(const float* __restrict__ f0,
                                               float* __restrict__ out,
                                               RandIniFx ri, NKey nk) {
  int b = blockIdx.y, c = blockIdx.x;
  int s = b * NCH + c;                 // lookback slot (monotone in block id)
  int base = c * CHUNK;
  int n = min(CHUNK, Tn - base);
  int tid = threadIdx.x;
  int warp = tid >> 5, lane = tid & 31;
  int s0 = tid * SPT;
  bool act = s0 < n;

  __shared__ float so[TPB * WPSP];    // 18.9KB staging, conflict-free
  __shared__ unsigned long long wsum[TPB / 32][DIMn];
  __shared__ unsigned long long s_excl[DIMn];

  float fv[SPT];
  if (act) {
    const float4 a = *reinterpret_cast<const float4*>(f0 + (size_t)b * Tn + base + s0);
    fv[0]=a.x; fv[1]=a.y; fv[2]=a.z; fv[3]=a.w;
  }

  // pass 1: thread-local u64 sums (rads recomputed in emit)
  unsigned long long run[DIMn];
#pragma unroll
  for (int h = 0; h < DIMn; h++) run[h] = 0ull;
  if (act) {
#pragma unroll
    for (int j = 0; j < SPT; j++) {
      bool first = (base + s0 + j) == 0;
#pragma unroll
      for (int h = 0; h < DIMn; h++) {
        unsigned long long rr = (unsigned long long)rad_fx(fv[j], h);
        if (first) rr += ri.v[b * DIMn + h];
        run[h] += rr;
      }
    }
  }

  // warp-inclusive scan per harmonic; run -> warp-exclusive prefix
#pragma unroll
  for (int h = 0; h < DIMn; h++) {
    unsigned long long acch = run[h];
    unsigned long long x = acch;
#pragma unroll
    for (int o = 1; o < 32; o <<= 1) {
      unsigned long long y = __shfl_up_sync(0xffffffffu, x, o);
      if (lane >= o) x += y;
    }
    if (lane == 31) wsum[warp][h] = x;
    run[h] = x - acch;
  }
  __syncthreads();

  // block-exclusive offset per thread; warp 0 also gets block total
#pragma unroll
  for (int h = 0; h < DIMn; h++) {
    unsigned long long wex = 0ull;
#pragma unroll
    for (int w = 0; w < TPB / 32; w++)
      if (w < warp) wex += wsum[w][h];
    run[h] += wex;
  }

  // ---- decoupled lookback (warp 0) ----
  if (warp == 0) {
    unsigned long long tot[DIMn];
#pragma unroll
    for (int h = 0; h < DIMn; h++)
      tot[h] = wsum[0][h] + wsum[1][h] + wsum[2][h] + wsum[3][h];

    // publish aggregate ASAP (skip for c==0: goes straight to prefix)
    if (lane == 0 && c > 0) {
#pragma unroll
      for (int h = 0; h < DIMn; h++) g_agg[s][h] = tot[h];
      asm volatile("st.release.gpu.global.u32 [%0], %1;"
                   :: "l"(&g_flag[s]), "r"(1u) : "memory");
    }

    unsigned long long excl[DIMn];
#pragma unroll
    for (int h = 0; h < DIMn; h++) excl[h] = 0ull;

    if (c > 0) {
      int cc = c - 1;
      for (;;) {
        int p = cc - lane;             // lane 0 = nearest predecessor
        unsigned st = 2u;
        if (p >= 0) {
          const unsigned int* fp = &g_flag[b * NCH + p];
          do {
            asm volatile("ld.acquire.gpu.global.u32 %0, [%1];"
                         : "=r"(st) : "l"(fp) : "memory");
          } while (st == 0u);
        }
        unsigned mask2 = __ballot_sync(0xffffffffu, st == 2u);
        int stop = __ffs(mask2) - 1;   // -1 if none: all aggs, keep walking
#pragma unroll
        for (int h = 0; h < DIMn; h++) {
          unsigned long long v = 0ull;
          if (p >= 0 && (stop < 0 || lane <= stop)) {
            v = (st == 2u) ? g_pref[b * NCH + p][h] : g_agg[b * NCH + p][h];
          }
#pragma unroll
          for (int o = 16; o > 0; o >>= 1)
            v += __shfl_xor_sync(0xffffffffu, v, o);
          excl[h] += v;
        }
        if (stop >= 0) break;
        cc -= 32;
      }
    }

    if (lane == 0) {
#pragma unroll
      for (int h = 0; h < DIMn; h++) {
        g_pref[s][h] = excl[h] + tot[h];
        s_excl[h] = excl[h];
      }
      asm volatile("st.release.gpu.global.u32 [%0], %1;"
                   :: "l"(&g_flag[s]), "r"(2u) : "memory");
    }
  }
  __syncthreads();

#pragma unroll
  for (int h = 0; h < DIMn; h++) run[h] += s_excl[h];

  // ---- emit ----
  if (act) {
#pragma unroll
    for (int j = 0; j < SPT; j++) {
      float v = fv[j];
      int t = base + s0 + j;
      uint32_t idxbase = ((uint32_t)(b * Tn + t)) * (uint32_t)DIMn;
      float uv  = (v > 0.0f) ? 1.0f : 0.0f;
      float amp = uv * 0.003f + (1.0f - uv) * (0.1f / 3.0f);
      int slot = tid * WPSP + j * DIMn;
#pragma unroll
      for (int h = 0; h < DIMn; h++) {
        unsigned long long rr = (unsigned long long)rad_fx(v, h);
        if (t == 0) rr += ri.v[b * DIMn + h];
        run[h] += rr;
        uint32_t p32 = (uint32_t)(run[h] >> 1);
        float sw = sine_from_p32(p32);

        uint32_t bits = rng_bits(nk.k0, nk.k1, idxbase + (uint32_t)h);
        float u = fmaxf(LO_NORMAL, fmaf(bits01(bits), 2.0f, LO_NORMAL));
        float nr = SQRT2F * erfinv_xla(u);

        so[slot + h] = sw * uv + amp * nr;
      }
    }
  }

  __syncthreads();
  int words = n * DIMn;
  size_t outbase = ((size_t)b * Tn + (size_t)base) * (size_t)DIMn;
  for (int w = tid; w < words; w += TPB) {
    int th = w / WPS;
    int of = w - th * WPS;
    out[outbase + (size_t)w] = so[th * WPSP + of];
  }
}

// ---------------- host ----------------
extern "C" void kernel_launch(void* const* d_in, const int* in_sizes, int n_in,
                              void* d_out, int out_size) {
  (void)in_sizes; (void)n_in; (void)out_size;
  const float* f0 = (const float*)d_in[0];
  float* out = (float*)d_out;

  uint32_t ik0, ik1, nk0, nk1;
  { uint32_t a, b;
    tf2x32(0u, 42u, 0u, 0u, a, b); ik0 = a; ik1 = b;
    tf2x32(0u, 42u, 0u, 1u, a, b); nk0 = a; nk1 = b; }

  RandIniFx ri;
  for (uint32_t i = 0; i < (uint32_t)(Bn * DIMn); i++) {
    uint32_t bits = rng_bits(ik0, ik1, i);
    float u = bits01(bits);
    if (u < 0.0f) u = 0.0f;
    ri.v[i] = (unsigned long long)((double)u * 8589934592.0);
  }
  for (int b = 0; b < Bn; b++) ri.v[b * DIMn] = 0ull;

  NKey nk{nk0, nk1};

  k_clear<<<(Bn * NCH + 511) / 512, 512>>>();
  dim3 grid(NCH, Bn);
  k_fused<<<grid, TPB>>>(f0, out, ri, nk);
}

// round 7
// speedup vs baseline: 1.5880x; 1.5880x over previous
#include <cuda_runtime.h>
#include <stdint.h>
#include <math.h>

constexpr int Bn   = 4;
constexpr int Tn   = 480000;
constexpr int DIMn = 9;
constexpr int CHUNK = 256;
constexpr int TPB   = 128;
constexpr int SPT   = CHUNK / TPB;               // 2
constexpr int NCH   = Tn / CHUNK;                // 1875 (exact)

constexpr float LO_NORMAL = -0.99999994f;
constexpr float SQRT2F    = 1.41421356237309504880f;
constexpr float RCP48K    = 2.08333333333333333e-05f;  // fl(1/48000)

constexpr int WPS  = SPT * DIMn;      // 18 words per thread
constexpr int WPSP = WPS + 1;         // padded stride 19

struct RandIniFx { uint32_t v[Bn * DIMn]; };
struct NKey      { uint32_t k0, k1; };

// per-(b,h) per-chunk u32 phase sums (2^-32 turns, mod 2^32);
// K2 converts in place to exclusive prefixes
__device__ uint32_t g_csum[Bn * DIMn * NCH];

// ---------------- threefry2x32-20 ----------------
__host__ __device__ __forceinline__ uint32_t rotl32(uint32_t x, int r) {
#ifdef __CUDA_ARCH__
  return __funnelshift_l(x, x, r);
#else
  return (x << r) | (x >> (32 - r));
#endif
}

__host__ __device__ __forceinline__ void tf2x32(uint32_t k0, uint32_t k1,
                                                uint32_t x0, uint32_t x1,
                                                uint32_t& o0, uint32_t& o1) {
  uint32_t k2 = k0 ^ k1 ^ 0x1BD11BDAu;
#define TFR(r) { x0 += x1; x1 = rotl32(x1, (r)); x1 ^= x0; }
  x0 += k0; x1 += k1;
  TFR(13) TFR(15) TFR(26) TFR(6)
  x0 += k1; x1 += k2 + 1u;
  TFR(17) TFR(29) TFR(16) TFR(24)
  x0 += k2; x1 += k0 + 2u;
  TFR(13) TFR(15) TFR(26) TFR(6)
  x0 += k0; x1 += k1 + 3u;
  TFR(17) TFR(29) TFR(16) TFR(24)
  x0 += k1; x1 += k2 + 4u;
  TFR(13) TFR(15) TFR(26) TFR(6)
  x0 += k2; x1 += k0 + 5u;
#undef TFR
  o0 = x0; o1 = x1;
}

__host__ __device__ __forceinline__ uint32_t rng_bits(uint32_t k0, uint32_t k1,
                                                      uint32_t idx) {
  uint32_t a, b;
  tf2x32(k0, k1, 0u, idx, a, b);
  return a ^ b;
}

__host__ __device__ __forceinline__ float bits01(uint32_t bits) {
  union { uint32_t u; float f; } c;
  c.u = (bits >> 9) | 0x3F800000u;
  return c.f - 1.0f;
}

// ---------------- XLA ErfInv32 (fast log; noise error budget ~1e-2) --------
__device__ __forceinline__ float erfinv_xla(float x) {
  float w = -__logf(fmaf(-x, x, 1.0f));
  float p;
  if (w < 5.0f) {
    w = w - 2.5f;
    p =             2.81022636e-08f;
    p = fmaf(p, w,  3.43273939e-07f);
    p = fmaf(p, w, -3.5233877e-06f);
    p = fmaf(p, w, -4.39150654e-06f);
    p = fmaf(p, w,  0.00021858087f);
    p = fmaf(p, w, -0.00125372503f);
    p = fmaf(p, w, -0.00417768164f);
    p = fmaf(p, w,  0.246640727f);
    p = fmaf(p, w,  1.50140941f);
  } else {
    w = sqrtf(w) - 3.0f;
    p =            -0.000200214257f;
    p = fmaf(p, w,  0.000100950558f);
    p = fmaf(p, w,  0.00134934322f);
    p = fmaf(p, w, -0.00367342844f);
    p = fmaf(p, w,  0.00573950773f);
    p = fmaf(p, w, -0.0076224613f);
    p = fmaf(p, w,  0.00943887047f);
    p = fmaf(p, w,  1.00167406f);
    p = fmaf(p, w,  2.83297682f);
  }
  return p * x;
}

// correctly-rounded x/48000 via Markstein (bit-identical to __fdiv_rn)
__device__ __forceinline__ float div48k(float x) {
  float q0 = __fmul_rn(x, RCP48K);
  float e  = fmaf(-48000.0f, q0, x);
  return fmaf(e, RCP48K, q0);
}

// rad in u32 fixed point, lsb = 2^-32 turns.
// rad is an exact multiple of 2^-33; *2^32 is exact (power-of-2 scale);
// F2I.RN rounds the half-integers to even: per-sample err <= 2^-33, no bias.
__device__ __forceinline__ uint32_t rad_fx32(float f0v, int h) {
  float rad = div48k(__fmul_rn(f0v, (float)(h + 1)));
  return __float2uint_rn(rad * 4294967296.0f);
}

// sin(2*pi*frac) * 0.1 from u32 phase (2^-32 turns). No MUFU.
__device__ __forceinline__ float sine_from_p32(uint32_t p32) {
  bool refl = (int32_t)(p32 + 0x40000000u) < 0;
  int32_t yi = refl ? (int32_t)(0x80000000u - p32) : (int32_t)p32;
  float x  = (float)yi * 4.65661287307739258e-10f;   // -> [-0.5, 0.5]
  float x2 = x * x;
  float p =            0.0821458866f;     // deg-9 odd poly for sin(pi x)
  p = fmaf(p, x2, -0.599264529f);
  p = fmaf(p, x2,  2.55016404f);
  p = fmaf(p, x2, -5.16771278f);
  p = fmaf(p, x2,  3.14159265f);
  return (x * 0.1f) * p;
}

// ---------------- K1: per-chunk u32 sums ----------------
__global__ void __launch_bounds__(TPB) k_chunksum(const float* __restrict__ f0, RandIniFx ri) {
  int b = blockIdx.y, c = blockIdx.x;
  int base = c * CHUNK;
  int tid = threadIdx.x;
  int s0 = tid * SPT;

  const float2 a = *reinterpret_cast<const float2*>(f0 + (size_t)b * Tn + base + s0);
  float fv[SPT] = {a.x, a.y};

  uint32_t acc[DIMn];
#pragma unroll
  for (int h = 0; h < DIMn; h++) acc[h] = 0u;
#pragma unroll
  for (int j = 0; j < SPT; j++) {
    bool first = (base + s0 + j) == 0;
#pragma unroll
    for (int h = 0; h < DIMn; h++) {
      uint32_t r = rad_fx32(fv[j], h);
      if (first) r += ri.v[b * DIMn + h];
      acc[h] += r;
    }
  }

#pragma unroll
  for (int h = 0; h < DIMn; h++) {
    uint32_t x = acc[h];
#pragma unroll
    for (int o = 16; o > 0; o >>= 1) x += __shfl_down_sync(0xffffffffu, x, o);
    acc[h] = x;
  }
  __shared__ uint32_t sm[TPB / 32][DIMn];
  int warp = tid >> 5, lane = tid & 31;
  if (lane == 0)
#pragma unroll
    for (int h = 0; h < DIMn; h++) sm[warp][h] = acc[h];
  __syncthreads();
  if (tid == 0) {
#pragma unroll
    for (int h = 0; h < DIMn; h++)
      g_csum[(b * DIMn + h) * NCH + c] = sm[0][h] + sm[1][h] + sm[2][h] + sm[3][h];
  }
}

// ---------------- K2: exclusive scan of chunk sums (36 series) -------------
__global__ void k_scan() {
  int s = blockIdx.x;
  int lane = threadIdx.x;
  constexpr int PER = (NCH + 31) / 32;   // 59
  uint32_t* row = &g_csum[(size_t)s * NCH];

  uint32_t v[PER];
  uint32_t tot = 0u;
  int st = lane * PER;
#pragma unroll
  for (int j = 0; j < PER; j++) {
    int c = st + j;
    v[j] = (c < NCH) ? row[c] : 0u;
    tot += v[j];
  }
  uint32_t x = tot;
#pragma unroll
  for (int o = 1; o < 32; o <<= 1) {
    uint32_t y = __shfl_up_sync(0xffffffffu, x, o);
    if (lane >= o) x += y;
  }
  uint32_t run = x - tot;
#pragma unroll
  for (int j = 0; j < PER; j++) {
    int c = st + j;
    if (c < NCH) {
      uint32_t old = v[j];
      row[c] = run;
      run += old;
    }
  }
}

// ---------------- K3: main (u32 phase, 9.7KB staging) ----------------------
__global__ void __launch_bounds__(TPB) k_main(const float* __restrict__ f0,
                                              float* __restrict__ out,
                                              RandIniFx ri, NKey nk) {
  int b = blockIdx.y, c = blockIdx.x;
  int base = c * CHUNK;
  int tid = threadIdx.x;
  int warp = tid >> 5, lane = tid & 31;
  int s0 = tid * SPT;

  __shared__ float so[TPB * WPSP];    // 128*19 floats = 9.7KB, conflict-free
  __shared__ uint32_t wsum[TPB / 32][DIMn];

  const float2 a = *reinterpret_cast<const float2*>(f0 + (size_t)b * Tn + base + s0);
  float fv[SPT] = {a.x, a.y};

  // pass 1: thread-local u32 sums (rads recomputed in emit)
  uint32_t run[DIMn];
#pragma unroll
  for (int h = 0; h < DIMn; h++) run[h] = 0u;
#pragma unroll
  for (int j = 0; j < SPT; j++) {
    bool first = (base + s0 + j) == 0;
#pragma unroll
    for (int h = 0; h < DIMn; h++) {
      uint32_t rr = rad_fx32(fv[j], h);
      if (first) rr += ri.v[b * DIMn + h];
      run[h] += rr;
    }
  }

  // warp-inclusive scan per harmonic; run -> warp-exclusive prefix
#pragma unroll
  for (int h = 0; h < DIMn; h++) {
    uint32_t acch = run[h];
    uint32_t x = acch;
#pragma unroll
    for (int o = 1; o < 32; o <<= 1) {
      uint32_t y = __shfl_up_sync(0xffffffffu, x, o);
      if (lane >= o) x += y;
    }
    if (lane == 31) wsum[warp][h] = x;
    run[h] = x - acch;
  }
  __syncthreads();

#pragma unroll
  for (int h = 0; h < DIMn; h++) {
    uint32_t wex = 0u;
#pragma unroll
    for (int w = 0; w < TPB / 32; w++)
      if (w < warp) wex += wsum[w][h];
    run[h] += g_csum[(b * DIMn + h) * NCH + c] + wex;
  }

  // ---- emit ----
#pragma unroll
  for (int j = 0; j < SPT; j++) {
    float v = fv[j];
    int t = base + s0 + j;
    uint32_t idxbase = ((uint32_t)(b * Tn + t)) * (uint32_t)DIMn;
    float uv  = (v > 0.0f) ? 1.0f : 0.0f;
    float amp = uv * 0.003f + (1.0f - uv) * (0.1f / 3.0f);
    int slot = tid * WPSP + j * DIMn;
#pragma unroll
    for (int h = 0; h < DIMn; h++) {
      uint32_t rr = rad_fx32(v, h);
      if (t == 0) rr += ri.v[b * DIMn + h];
      run[h] += rr;
      float sw = sine_from_p32(run[h]);

      uint32_t bits = rng_bits(nk.k0, nk.k1, idxbase + (uint32_t)h);
      float u = fmaxf(LO_NORMAL, fmaf(bits01(bits), 2.0f, LO_NORMAL));
      float nr = SQRT2F * erfinv_xla(u);

      so[slot + h] = sw * uv + amp * nr;
    }
  }

  __syncthreads();
  constexpr int WORDS = CHUNK * DIMn;       // 2304
  size_t outbase = ((size_t)b * Tn + (size_t)base) * (size_t)DIMn;
#pragma unroll
  for (int i = 0; i < WORDS / TPB; i++) {
    int w = i * TPB + tid;
    int th = w / WPS;
    int of = w - th * WPS;
    out[outbase + (size_t)w] = so[th * WPSP + of];
  }
}

// ---------------- host ----------------
extern "C" void kernel_launch(void* const* d_in, const int* in_sizes, int n_in,
                              void* d_out, int out_size) {
  (void)in_sizes; (void)n_in; (void)out_size;
  const float* f0 = (const float*)d_in[0];
  float* out = (float*)d_out;

  uint32_t ik0, ik1, nk0, nk1;
  { uint32_t a, b;
    tf2x32(0u, 42u, 0u, 0u, a, b); ik0 = a; ik1 = b;
    tf2x32(0u, 42u, 0u, 1u, a, b); nk0 = a; nk1 = b; }

  RandIniFx ri;
  for (uint32_t i = 0; i < (uint32_t)(Bn * DIMn); i++) {
    uint32_t bits = rng_bits(ik0, ik1, i);
    float u = bits01(bits);
    if (u < 0.0f) u = 0.0f;
    ri.v[i] = (uint32_t)((double)u * 4294967296.0);  // u mult of 2^-23 -> exact
  }
  for (int b = 0; b < Bn; b++) ri.v[b * DIMn] = 0u;

  NKey nk{nk0, nk1};

  dim3 grid(NCH, Bn);
  k_chunksum<<<grid, TPB>>>(f0, ri);
  k_scan<<<Bn * DIMn, 32>>>();
  k_main<<<grid, TPB>>>(f0, out, ri, nk);
}

// round 8
// speedup vs baseline: 1.6464x; 1.0367x over previous
#include <cuda_runtime.h>
#include <stdint.h>
#include <math.h>

constexpr int Bn   = 4;
constexpr int Tn   = 480000;
constexpr int DIMn = 9;
constexpr int CHUNK = 256;
constexpr int TPB   = 128;
constexpr int SPT   = CHUNK / TPB;               // 2
constexpr int NCH   = Tn / CHUNK;                // 1875 (exact)

constexpr float LO_NORMAL = -0.99999994f;
constexpr float SQRT2F    = 1.41421356237309504880f;
constexpr float RCP48K    = 2.08333333333333333e-05f;  // fl(1/48000)

struct RandIniFx { uint32_t v[Bn * DIMn]; };
struct NKey      { uint32_t k0, k1; };

// per-(b,h) per-chunk u32 phase sums (2^-32 turns, mod 2^32);
// K2 converts in place to exclusive prefixes
__device__ uint32_t g_csum[Bn * DIMn * NCH];

// ---------------- threefry2x32-20 ----------------
__host__ __device__ __forceinline__ uint32_t rotl32(uint32_t x, int r) {
#ifdef __CUDA_ARCH__
  return __funnelshift_l(x, x, r);
#else
  return (x << r) | (x >> (32 - r));
#endif
}

__host__ __device__ __forceinline__ void tf2x32(uint32_t k0, uint32_t k1,
                                                uint32_t x0, uint32_t x1,
                                                uint32_t& o0, uint32_t& o1) {
  uint32_t k2 = k0 ^ k1 ^ 0x1BD11BDAu;
#define TFR(r) { x0 += x1; x1 = rotl32(x1, (r)); x1 ^= x0; }
  x0 += k0; x1 += k1;
  TFR(13) TFR(15) TFR(26) TFR(6)
  x0 += k1; x1 += k2 + 1u;
  TFR(17) TFR(29) TFR(16) TFR(24)
  x0 += k2; x1 += k0 + 2u;
  TFR(13) TFR(15) TFR(26) TFR(6)
  x0 += k0; x1 += k1 + 3u;
  TFR(17) TFR(29) TFR(16) TFR(24)
  x0 += k1; x1 += k2 + 4u;
  TFR(13) TFR(15) TFR(26) TFR(6)
  x0 += k2; x1 += k0 + 5u;
#undef TFR
  o0 = x0; o1 = x1;
}

__host__ __device__ __forceinline__ uint32_t rng_bits(uint32_t k0, uint32_t k1,
                                                      uint32_t idx) {
  uint32_t a, b;
  tf2x32(k0, k1, 0u, idx, a, b);
  return a ^ b;
}

__host__ __device__ __forceinline__ float bits01(uint32_t bits) {
  union { uint32_t u; float f; } c;
  c.u = (bits >> 9) | 0x3F800000u;
  return c.f - 1.0f;
}

// ---------------- XLA ErfInv32 (fast log; noise error budget ~1e-2) --------
__device__ __forceinline__ float erfinv_xla(float x) {
  float w = -__logf(fmaf(-x, x, 1.0f));
  float p;
  if (w < 5.0f) {
    w = w - 2.5f;
    p =             2.81022636e-08f;
    p = fmaf(p, w,  3.43273939e-07f);
    p = fmaf(p, w, -3.5233877e-06f);
    p = fmaf(p, w, -4.39150654e-06f);
    p = fmaf(p, w,  0.00021858087f);
    p = fmaf(p, w, -0.00125372503f);
    p = fmaf(p, w, -0.00417768164f);
    p = fmaf(p, w,  0.246640727f);
    p = fmaf(p, w,  1.50140941f);
  } else {
    w = sqrtf(w) - 3.0f;
    p =            -0.000200214257f;
    p = fmaf(p, w,  0.000100950558f);
    p = fmaf(p, w,  0.00134934322f);
    p = fmaf(p, w, -0.00367342844f);
    p = fmaf(p, w,  0.00573950773f);
    p = fmaf(p, w, -0.0076224613f);
    p = fmaf(p, w,  0.00943887047f);
    p = fmaf(p, w,  1.00167406f);
    p = fmaf(p, w,  2.83297682f);
  }
  return p * x;
}

// correctly-rounded x/48000 via Markstein (bit-identical to __fdiv_rn)
__device__ __forceinline__ float div48k(float x) {
  float q0 = __fmul_rn(x, RCP48K);
  float e  = fmaf(-48000.0f, q0, x);
  return fmaf(e, RCP48K, q0);
}

// rad in u32 fixed point, lsb = 2^-32 turns (exact *2^32, RN-even on half-lsb)
__device__ __forceinline__ uint32_t rad_fx32(float f0v, int h) {
  float rad = div48k(__fmul_rn(f0v, (float)(h + 1)));
  return __float2uint_rn(rad * 4294967296.0f);
}

// sin(2*pi*frac) * 0.1 from u32 phase (2^-32 turns). No MUFU.
__device__ __forceinline__ float sine_from_p32(uint32_t p32) {
  bool refl = (int32_t)(p32 + 0x40000000u) < 0;
  int32_t yi = refl ? (int32_t)(0x80000000u - p32) : (int32_t)p32;
  float x  = (float)yi * 4.65661287307739258e-10f;   // -> [-0.5, 0.5]
  float x2 = x * x;
  float p =            0.0821458866f;     // deg-9 odd poly for sin(pi x)
  p = fmaf(p, x2, -0.599264529f);
  p = fmaf(p, x2,  2.55016404f);
  p = fmaf(p, x2, -5.16771278f);
  p = fmaf(p, x2,  3.14159265f);
  return (x * 0.1f) * p;
}

// ---------------- K1: per-chunk u32 sums ----------------
__global__ void __launch_bounds__(TPB) k_chunksum(const float* __restrict__ f0, RandIniFx ri) {
  int b = blockIdx.y, c = blockIdx.x;
  int base = c * CHUNK;
  int tid = threadIdx.x;
  int s0 = tid * SPT;

  const float2 a = *reinterpret_cast<const float2*>(f0 + (size_t)b * Tn + base + s0);
  float fv[SPT] = {a.x, a.y};

  uint32_t acc[DIMn];
#pragma unroll
  for (int h = 0; h < DIMn; h++) acc[h] = 0u;
#pragma unroll
  for (int j = 0; j < SPT; j++) {
    bool first = (base + s0 + j) == 0;
#pragma unroll
    for (int h = 0; h < DIMn; h++) {
      uint32_t r = rad_fx32(fv[j], h);
      if (first) r += ri.v[b * DIMn + h];
      acc[h] += r;
    }
  }

#pragma unroll
  for (int h = 0; h < DIMn; h++) {
    uint32_t x = acc[h];
#pragma unroll
    for (int o = 16; o > 0; o >>= 1) x += __shfl_down_sync(0xffffffffu, x, o);
    acc[h] = x;
  }
  __shared__ uint32_t sm[TPB / 32][DIMn];
  int warp = tid >> 5, lane = tid & 31;
  if (lane == 0)
#pragma unroll
    for (int h = 0; h < DIMn; h++) sm[warp][h] = acc[h];
  __syncthreads();
  if (tid == 0) {
#pragma unroll
    for (int h = 0; h < DIMn; h++)
      g_csum[(b * DIMn + h) * NCH + c] = sm[0][h] + sm[1][h] + sm[2][h] + sm[3][h];
  }
}

// ---------------- K2: exclusive scan of chunk sums (36 series) -------------
__global__ void k_scan() {
  int s = blockIdx.x;
  int lane = threadIdx.x;
  constexpr int PER = (NCH + 31) / 32;   // 59
  uint32_t* row = &g_csum[(size_t)s * NCH];

  uint32_t v[PER];
  uint32_t tot = 0u;
  int st = lane * PER;
#pragma unroll
  for (int j = 0; j < PER; j++) {
    int c = st + j;
    v[j] = (c < NCH) ? row[c] : 0u;
    tot += v[j];
  }
  uint32_t x = tot;
#pragma unroll
  for (int o = 1; o < 32; o <<= 1) {
    uint32_t y = __shfl_up_sync(0xffffffffu, x, o);
    if (lane >= o) x += y;
  }
  uint32_t run = x - tot;
#pragma unroll
  for (int j = 0; j < PER; j++) {
    int c = st + j;
    if (c < NCH) {
      uint32_t old = v[j];
      row[c] = run;
      run += old;
    }
  }
}

// ---------------- K3: main (direct staging layout, div-free writeout) ------
__global__ void __launch_bounds__(TPB) k_main(const float* __restrict__ f0,
                                              float* __restrict__ out,
                                              RandIniFx ri, NKey nk) {
  int b = blockIdx.y, c = blockIdx.x;
  int base = c * CHUNK;
  int tid = threadIdx.x;
  int warp = tid >> 5, lane = tid & 31;
  int s0 = tid * SPT;

  __shared__ float so[CHUNK * DIMn];  // 2304 floats = 9.2KB, natural layout
  __shared__ uint32_t wsum[TPB / 32][DIMn];

  const float2 a = *reinterpret_cast<const float2*>(f0 + (size_t)b * Tn + base + s0);
  float fv[SPT] = {a.x, a.y};

  // pass 1: thread-local u32 sums (rads recomputed in emit)
  uint32_t run[DIMn];
#pragma unroll
  for (int h = 0; h < DIMn; h++) run[h] = 0u;
#pragma unroll
  for (int j = 0; j < SPT; j++) {
    bool first = (base + s0 + j) == 0;
#pragma unroll
    for (int h = 0; h < DIMn; h++) {
      uint32_t rr = rad_fx32(fv[j], h);
      if (first) rr += ri.v[b * DIMn + h];
      run[h] += rr;
    }
  }

  // warp-inclusive scan per harmonic; run -> warp-exclusive prefix
#pragma unroll
  for (int h = 0; h < DIMn; h++) {
    uint32_t acch = run[h];
    uint32_t x = acch;
#pragma unroll
    for (int o = 1; o < 32; o <<= 1) {
      uint32_t y = __shfl_up_sync(0xffffffffu, x, o);
      if (lane >= o) x += y;
    }
    if (lane == 31) wsum[warp][h] = x;
    run[h] = x - acch;
  }
  __syncthreads();

#pragma unroll
  for (int h = 0; h < DIMn; h++) {
    uint32_t wex = 0u;
#pragma unroll
    for (int w = 0; w < TPB / 32; w++)
      if (w < warp) wex += wsum[w][h];
    run[h] += g_csum[(b * DIMn + h) * NCH + c] + wex;
  }

  // ---- emit: direct layout so[sample*9 + h] (2-way STS conflict, cheap) ----
#pragma unroll
  for (int j = 0; j < SPT; j++) {
    float v = fv[j];
    int t = base + s0 + j;
    uint32_t idxbase = ((uint32_t)(b * Tn + t)) * (uint32_t)DIMn;
    float uv  = (v > 0.0f) ? 1.0f : 0.0f;
    float amp = uv * 0.003f + (1.0f - uv) * (0.1f / 3.0f);
    int slot = (s0 + j) * DIMn;
#pragma unroll
    for (int h = 0; h < DIMn; h++) {
      uint32_t rr = rad_fx32(v, h);
      if (t == 0) rr += ri.v[b * DIMn + h];
      run[h] += rr;
      float sw = sine_from_p32(run[h]);

      uint32_t bits = rng_bits(nk.k0, nk.k1, idxbase + (uint32_t)h);
      float u = fmaxf(LO_NORMAL, fmaf(bits01(bits), 2.0f, LO_NORMAL));
      float nr = SQRT2F * erfinv_xla(u);

      so[slot + h] = sw * uv + amp * nr;
    }
  }

  __syncthreads();
  // ---- writeout: linear float2, no division, coalesced ----
  constexpr int PAIRS = CHUNK * DIMn / 2;      // 1152
  size_t outbase = ((size_t)b * Tn + (size_t)base) * (size_t)DIMn;
  const float2* so2 = reinterpret_cast<const float2*>(so);
  float2* out2 = reinterpret_cast<float2*>(out + outbase);
#pragma unroll
  for (int i = 0; i < PAIRS / TPB; i++)        // 9 iterations
    out2[i * TPB + tid] = so2[i * TPB + tid];
}

// ---------------- host ----------------
extern "C" void kernel_launch(void* const* d_in, const int* in_sizes, int n_in,
                              void* d_out, int out_size) {
  (void)in_sizes; (void)n_in; (void)out_size;
  const float* f0 = (const float*)d_in[0];
  float* out = (float*)d_out;

  uint32_t ik0, ik1, nk0, nk1;
  { uint32_t a, b;
    tf2x32(0u, 42u, 0u, 0u, a, b); ik0 = a; ik1 = b;
    tf2x32(0u, 42u, 0u, 1u, a, b); nk0 = a; nk1 = b; }

  RandIniFx ri;
  for (uint32_t i = 0; i < (uint32_t)(Bn * DIMn); i++) {
    uint32_t bits = rng_bits(ik0, ik1, i);
    float u = bits01(bits);
    if (u < 0.0f) u = 0.0f;
    ri.v[i] = (uint32_t)((double)u * 4294967296.0);  // u mult of 2^-23 -> exact
  }
  for (int b = 0; b < Bn; b++) ri.v[b * DIMn] = 0u;

  NKey nk{nk0, nk1};

  dim3 grid(NCH, Bn);
  k_chunksum<<<grid, TPB>>>(f0, ri);
  k_scan<<<Bn * DIMn, 32>>>();
  k_main<<<grid, TPB>>>(f0, out, ri, nk);
}

// round 9
// speedup vs baseline: 1.9863x; 1.2065x over previous
#include <cuda_runtime.h>
#include <stdint.h>
#include <math.h>

constexpr int Bn   = 4;
constexpr int Tn   = 480000;
constexpr int DIMn = 9;
constexpr int CHUNK = 256;
constexpr int TPB   = 128;
constexpr int SPT   = CHUNK / TPB;               // 2
constexpr int NCH   = Tn / CHUNK;                // 1875 (exact)
constexpr int K1_CPB = 8;                        // chunks per K1 block
constexpr int K1_GX  = (NCH + K1_CPB - 1) / K1_CPB;  // 235

constexpr float LO_NORMAL = -0.99999994f;
constexpr float SQRT2F    = 1.41421356237309504880f;
constexpr float RCP48K    = 2.08333333333333333e-05f;  // fl(1/48000)

struct RandIniFx { uint32_t v[Bn * DIMn]; };
struct NKey      { uint32_t k0, k1; };

// per-(b,h) per-chunk EXACT u32 phase sums (2^-32 turns, mod 2^32);
// K2 converts in place to exclusive prefixes. No ini here (K3 adds it).
__device__ uint32_t g_csum[Bn * DIMn * NCH];

// ---------------- threefry2x32-20 ----------------
__host__ __device__ __forceinline__ uint32_t rotl32(uint32_t x, int r) {
#ifdef __CUDA_ARCH__
  return __funnelshift_l(x, x, r);
#else
  return (x << r) | (x >> (32 - r));
#endif
}

__host__ __device__ __forceinline__ void tf2x32(uint32_t k0, uint32_t k1,
                                                uint32_t x0, uint32_t x1,
                                                uint32_t& o0, uint32_t& o1) {
  uint32_t k2 = k0 ^ k1 ^ 0x1BD11BDAu;
#define TFR(r) { x0 += x1; x1 = rotl32(x1, (r)); x1 ^= x0; }
  x0 += k0; x1 += k1;
  TFR(13) TFR(15) TFR(26) TFR(6)
  x0 += k1; x1 += k2 + 1u;
  TFR(17) TFR(29) TFR(16) TFR(24)
  x0 += k2; x1 += k0 + 2u;
  TFR(13) TFR(15) TFR(26) TFR(6)
  x0 += k0; x1 += k1 + 3u;
  TFR(17) TFR(29) TFR(16) TFR(24)
  x0 += k1; x1 += k2 + 4u;
  TFR(13) TFR(15) TFR(26) TFR(6)
  x0 += k2; x1 += k0 + 5u;
#undef TFR
  o0 = x0; o1 = x1;
}

__host__ __device__ __forceinline__ uint32_t rng_bits(uint32_t k0, uint32_t k1,
                                                      uint32_t idx) {
  uint32_t a, b;
  tf2x32(k0, k1, 0u, idx, a, b);
  return a ^ b;
}

__host__ __device__ __forceinline__ float bits01(uint32_t bits) {
  union { uint32_t u; float f; } c;
  c.u = (bits >> 9) | 0x3F800000u;
  return c.f - 1.0f;
}

// ---------------- XLA ErfInv32 (fast log; noise error budget ~1e-2) --------
__device__ __forceinline__ float erfinv_xla(float x) {
  float w = -__logf(fmaf(-x, x, 1.0f));
  float p;
  if (w < 5.0f) {
    w = w - 2.5f;
    p =             2.81022636e-08f;
    p = fmaf(p, w,  3.43273939e-07f);
    p = fmaf(p, w, -3.5233877e-06f);
    p = fmaf(p, w, -4.39150654e-06f);
    p = fmaf(p, w,  0.00021858087f);
    p = fmaf(p, w, -0.00125372503f);
    p = fmaf(p, w, -0.00417768164f);
    p = fmaf(p, w,  0.246640727f);
    p = fmaf(p, w,  1.50140941f);
  } else {
    w = sqrtf(w) - 3.0f;
    p =            -0.000200214257f;
    p = fmaf(p, w,  0.000100950558f);
    p = fmaf(p, w,  0.00134934322f);
    p = fmaf(p, w, -0.00367342844f);
    p = fmaf(p, w,  0.00573950773f);
    p = fmaf(p, w, -0.0076224613f);
    p = fmaf(p, w,  0.00943887047f);
    p = fmaf(p, w,  1.00167406f);
    p = fmaf(p, w,  2.83297682f);
  }
  return p * x;
}

// correctly-rounded x/48000 via Markstein (bit-identical to __fdiv_rn)
__device__ __forceinline__ float div48k(float x) {
  float q0 = __fmul_rn(x, RCP48K);
  float e  = fmaf(-48000.0f, q0, x);
  return fmaf(e, RCP48K, q0);
}

// rad in u32 fixed point, lsb = 2^-32 turns (exact *2^32, RN on half-lsb)
__device__ __forceinline__ uint32_t rad_fx32(float f0v, int h) {
  float rad = div48k(__fmul_rn(f0v, (float)(h + 1)));
  return __float2uint_rn(rad * 4294967296.0f);
}

// 0.1 * sin(2*pi*frac(p32/2^32)) — full-period deg-13 odd Taylor, no alu ops
__device__ __forceinline__ float sine01_full(uint32_t p32) {
  float y  = (float)(int32_t)p32 * 1.46291807926715968e-09f;  // 2*pi/2^32
  float y2 = y * y;
  float q =             1.60590438e-10f;   // 1/13!
  q = fmaf(q, y2, -2.50521084e-08f);       // -1/11!
  q = fmaf(q, y2,  2.75573192e-06f);       //  1/9!
  q = fmaf(q, y2, -1.98412698e-04f);       // -1/7!
  q = fmaf(q, y2,  8.33333333e-03f);       //  1/5!
  q = fmaf(q, y2, -0.166666667f);          // -1/3!
  float t = y * y2;
  float s = fmaf(t, q, y);                 // sin(y)
  return 0.1f * s;
}

// ---------------- K1: exact per-chunk 9-harmonic sums (MLP=4) --------------
__global__ void __launch_bounds__(TPB) k_chunksum(const float* __restrict__ f0) {
  int b = blockIdx.y;
  int tid = threadIdx.x;
  int seg = tid >> 4, sub = tid & 15;          // 16 threads per chunk
  int c = blockIdx.x * K1_CPB + seg;
  bool valid = c < NCH;
  int s_base = valid ? c * CHUNK + sub * 16 : 0;

  const float4* p = reinterpret_cast<const float4*>(f0 + (size_t)b * Tn + s_base);
  float4 q0 = p[0], q1 = p[1], q2 = p[2], q3 = p[3];
  float fv[16] = {q0.x,q0.y,q0.z,q0.w, q1.x,q1.y,q1.z,q1.w,
                  q2.x,q2.y,q2.z,q2.w, q3.x,q3.y,q3.z,q3.w};

  uint32_t acc[DIMn];
#pragma unroll
  for (int h = 0; h < DIMn; h++) acc[h] = 0u;
#pragma unroll
  for (int j = 0; j < 16; j++)
#pragma unroll
    for (int h = 0; h < DIMn; h++)
      acc[h] += rad_fx32(fv[j], h);

  // reduce across the 16-lane segment
#pragma unroll
  for (int h = 0; h < DIMn; h++) {
    uint32_t x = acc[h];
#pragma unroll
    for (int o = 8; o > 0; o >>= 1) x += __shfl_down_sync(0xffffffffu, x, o, 16);
    acc[h] = x;
  }
  if (sub == 0 && valid) {
#pragma unroll
    for (int h = 0; h < DIMn; h++)
      g_csum[(b * DIMn + h) * NCH + c] = acc[h];
  }
}

// ---------------- K2: exclusive scan of chunk sums (36 series) -------------
__global__ void k_scan() {
  int s = blockIdx.x;
  int lane = threadIdx.x;
  constexpr int PER = (NCH + 31) / 32;   // 59
  uint32_t* row = &g_csum[(size_t)s * NCH];

  uint32_t v[PER];
  uint32_t tot = 0u;
  int st = lane * PER;
#pragma unroll
  for (int j = 0; j < PER; j++) {
    int c = st + j;
    v[j] = (c < NCH) ? row[c] : 0u;
    tot += v[j];
  }
  uint32_t x = tot;
#pragma unroll
  for (int o = 1; o < 32; o <<= 1) {
    uint32_t y = __shfl_up_sync(0xffffffffu, x, o);
    if (lane >= o) x += y;
  }
  uint32_t run = x - tot;
#pragma unroll
  for (int j = 0; j < PER; j++) {
    int c = st + j;
    if (c < NCH) {
      uint32_t old = v[j];
      row[c] = run;
      run += old;
    }
  }
}

// ---------------- K3: main — fundamental-only scan, IMAD harmonic phases ---
__global__ void __launch_bounds__(TPB) k_main(const float* __restrict__ f0,
                                              float* __restrict__ out,
                                              RandIniFx ri, NKey nk) {
  int b = blockIdx.y, c = blockIdx.x;
  int base = c * CHUNK;
  int tid = threadIdx.x;
  int warp = tid >> 5, lane = tid & 31;
  int s0 = tid * SPT;

  __shared__ float so[CHUNK * DIMn];  // 9.2KB staging, natural layout
  __shared__ uint32_t wsum[TPB / 32];

  const float2 a = *reinterpret_cast<const float2*>(f0 + (size_t)b * Tn + base + s0);
  float fv[SPT] = {a.x, a.y};

  // fundamental rads (cached for emit)
  uint32_t r0[SPT] = {rad_fx32(fv[0], 0), rad_fx32(fv[1], 0)};
  uint32_t a0 = r0[0] + r0[1];

  // warp scan (fundamental only)
  uint32_t x = a0;
#pragma unroll
  for (int o = 1; o < 32; o <<= 1) {
    uint32_t y = __shfl_up_sync(0xffffffffu, x, o);
    if (lane >= o) x += y;
  }
  if (lane == 31) wsum[warp] = x;
  uint32_t w0 = x - a0;               // thread-exclusive within-chunk prefix
  __syncthreads();
#pragma unroll
  for (int w = 0; w < TPB / 32; w++)
    if (w < warp) w0 += wsum[w];

  // exact per-chunk bases: chunk-exclusive harmonic prefix + initial phase
  uint32_t bse[DIMn];
#pragma unroll
  for (int h = 0; h < DIMn; h++)
    bse[h] = g_csum[(b * DIMn + h) * NCH + c] + ri.v[b * DIMn + h];

  // ---- emit ----
#pragma unroll
  for (int j = 0; j < SPT; j++) {
    float v = fv[j];
    int t = base + s0 + j;
    w0 += r0[j];                       // within-chunk inclusive fundamental
    uint32_t idxbase = ((uint32_t)(b * Tn + t)) * (uint32_t)DIMn;
    float uv  = (v > 0.0f) ? 1.0f : 0.0f;
    float amp = uv * 0.003f + (1.0f - uv) * (0.1f / 3.0f);
    int slot = (s0 + j) * DIMn;
#pragma unroll
    for (int h = 0; h < DIMn; h++) {
      uint32_t p32 = bse[h] + (uint32_t)(h + 1) * w0;   // 1 IMAD
      float sw = sine01_full(p32);

      uint32_t bits = rng_bits(nk.k0, nk.k1, idxbase + (uint32_t)h);
      float u = fmaxf(LO_NORMAL, fmaf(bits01(bits), 2.0f, LO_NORMAL));
      float nr = SQRT2F * erfinv_xla(u);

      so[slot + h] = sw * uv + amp * nr;
    }
  }

  __syncthreads();
  // ---- writeout: linear float2, coalesced ----
  constexpr int PAIRS = CHUNK * DIMn / 2;      // 1152
  size_t outbase = ((size_t)b * Tn + (size_t)base) * (size_t)DIMn;
  const float2* so2 = reinterpret_cast<const float2*>(so);
  float2* out2 = reinterpret_cast<float2*>(out + outbase);
#pragma unroll
  for (int i = 0; i < PAIRS / TPB; i++)        // 9 iterations
    out2[i * TPB + tid] = so2[i * TPB + tid];
}

// ---------------- host ----------------
extern "C" void kernel_launch(void* const* d_in, const int* in_sizes, int n_in,
                              void* d_out, int out_size) {
  (void)in_sizes; (void)n_in; (void)out_size;
  const float* f0 = (const float*)d_in[0];
  float* out = (float*)d_out;

  uint32_t ik0, ik1, nk0, nk1;
  { uint32_t a, b;
    tf2x32(0u, 42u, 0u, 0u, a, b); ik0 = a; ik1 = b;
    tf2x32(0u, 42u, 0u, 1u, a, b); nk0 = a; nk1 = b; }

  RandIniFx ri;
  for (uint32_t i = 0; i < (uint32_t)(Bn * DIMn); i++) {
    uint32_t bits = rng_bits(ik0, ik1, i);
    float u = bits01(bits);
    if (u < 0.0f) u = 0.0f;
    ri.v[i] = (uint32_t)((double)u * 4294967296.0);  // u mult of 2^-23 -> exact
  }
  for (int b = 0; b < Bn; b++) ri.v[b * DIMn] = 0u;

  NKey nk{nk0, nk1};

  dim3 grid1(K1_GX, Bn);
  k_chunksum<<<grid1, TPB>>>(f0);
  k_scan<<<Bn * DIMn, 32>>>();
  dim3 grid3(NCH, Bn);
  k_main<<<grid3, TPB>>>(f0, out, ri, nk);
}

// round 10
// speedup vs baseline: 2.1380x; 1.0763x over previous
#include <cuda_runtime.h>
#include <stdint.h>
#include <math.h>

constexpr int Bn   = 4;
constexpr int Tn   = 480000;
constexpr int DIMn = 9;
constexpr int CHUNK = 256;
constexpr int TPB   = 128;
constexpr int SPT   = CHUNK / TPB;               // 2
constexpr int NCH   = Tn / CHUNK;                // 1875 (exact)
constexpr int K1_CPB = 8;                        // chunks per K1 block
constexpr int K1_GX  = (NCH + K1_CPB - 1) / K1_CPB;  // 235

constexpr float LO_NORMAL = -0.99999994f;
constexpr float SQRT2F    = 1.41421356237309504880f;
constexpr float RCP48K    = 2.08333333333333333e-05f;  // fl(1/48000)

struct RandIniFx { uint32_t v[Bn * DIMn]; };
struct NKey      { uint32_t k0, k1; };

// per-(b) per-chunk EXACT fundamental phase sums (2^-32 turns, mod 2^32);
// K2 converts in place to exclusive prefixes.
__device__ uint32_t g_pre0[Bn * NCH];

// ---------------- threefry2x32-20 ----------------
__host__ __device__ __forceinline__ uint32_t rotl32(uint32_t x, int r) {
#ifdef __CUDA_ARCH__
  return __funnelshift_l(x, x, r);
#else
  return (x << r) | (x >> (32 - r));
#endif
}

__host__ __device__ __forceinline__ void tf2x32(uint32_t k0, uint32_t k1,
                                                uint32_t x0, uint32_t x1,
                                                uint32_t& o0, uint32_t& o1) {
  uint32_t k2 = k0 ^ k1 ^ 0x1BD11BDAu;
#define TFR(r) { x0 += x1; x1 = rotl32(x1, (r)); x1 ^= x0; }
  x0 += k0; x1 += k1;
  TFR(13) TFR(15) TFR(26) TFR(6)
  x0 += k1; x1 += k2 + 1u;
  TFR(17) TFR(29) TFR(16) TFR(24)
  x0 += k2; x1 += k0 + 2u;
  TFR(13) TFR(15) TFR(26) TFR(6)
  x0 += k0; x1 += k1 + 3u;
  TFR(17) TFR(29) TFR(16) TFR(24)
  x0 += k1; x1 += k2 + 4u;
  TFR(13) TFR(15) TFR(26) TFR(6)
  x0 += k2; x1 += k0 + 5u;
#undef TFR
  o0 = x0; o1 = x1;
}

__host__ __device__ __forceinline__ uint32_t rng_bits(uint32_t k0, uint32_t k1,
                                                      uint32_t idx) {
  uint32_t a, b;
  tf2x32(k0, k1, 0u, idx, a, b);
  return a ^ b;
}

__host__ __device__ __forceinline__ float bits01(uint32_t bits) {
  union { uint32_t u; float f; } c;
  c.u = (bits >> 9) | 0x3F800000u;
  return c.f - 1.0f;
}

// ---------------- XLA ErfInv32 (fast log; noise error budget ~1e-2) --------
__device__ __forceinline__ float erfinv_xla(float x) {
  float w = -__logf(fmaf(-x, x, 1.0f));
  float p;
  if (w < 5.0f) {
    w = w - 2.5f;
    p =             2.81022636e-08f;
    p = fmaf(p, w,  3.43273939e-07f);
    p = fmaf(p, w, -3.5233877e-06f);
    p = fmaf(p, w, -4.39150654e-06f);
    p = fmaf(p, w,  0.00021858087f);
    p = fmaf(p, w, -0.00125372503f);
    p = fmaf(p, w, -0.00417768164f);
    p = fmaf(p, w,  0.246640727f);
    p = fmaf(p, w,  1.50140941f);
  } else {
    w = sqrtf(w) - 3.0f;
    p =            -0.000200214257f;
    p = fmaf(p, w,  0.000100950558f);
    p = fmaf(p, w,  0.00134934322f);
    p = fmaf(p, w, -0.00367342844f);
    p = fmaf(p, w,  0.00573950773f);
    p = fmaf(p, w, -0.0076224613f);
    p = fmaf(p, w,  0.00943887047f);
    p = fmaf(p, w,  1.00167406f);
    p = fmaf(p, w,  2.83297682f);
  }
  return p * x;
}

// correctly-rounded x/48000 via Markstein (bit-identical to __fdiv_rn)
__device__ __forceinline__ float div48k(float x) {
  float q0 = __fmul_rn(x, RCP48K);
  float e  = fmaf(-48000.0f, q0, x);
  return fmaf(e, RCP48K, q0);
}

// fundamental rad in u32 fixed point, lsb = 2^-32 turns
__device__ __forceinline__ uint32_t rad0_fx32(float f0v) {
  float rad = div48k(f0v);
  return __float2uint_rn(rad * 4294967296.0f);
}

// 0.1 * sin(2*pi*frac(p32/2^32)) — full-period deg-13 odd Taylor, no alu ops
__device__ __forceinline__ float sine01_full(uint32_t p32) {
  float y  = (float)(int32_t)p32 * 1.46291807926715968e-09f;  // 2*pi/2^32
  float y2 = y * y;
  float q =             1.60590438e-10f;   // 1/13!
  q = fmaf(q, y2, -2.50521084e-08f);       // -1/11!
  q = fmaf(q, y2,  2.75573192e-06f);       //  1/9!
  q = fmaf(q, y2, -1.98412698e-04f);       // -1/7!
  q = fmaf(q, y2,  8.33333333e-03f);       //  1/5!
  q = fmaf(q, y2, -0.166666667f);          // -1/3!
  float t = y * y2;
  float s = fmaf(t, q, y);                 // sin(y)
  return 0.1f * s;
}

// ---------------- K1: exact per-chunk FUNDAMENTAL sums (MLP=4) -------------
__global__ void __launch_bounds__(TPB) k_chunksum0(const float* __restrict__ f0) {
  int b = blockIdx.y;
  int tid = threadIdx.x;
  int seg = tid >> 4, sub = tid & 15;          // 16 threads per chunk
  int c = blockIdx.x * K1_CPB + seg;
  bool valid = c < NCH;
  int s_base = valid ? c * CHUNK + sub * 16 : 0;

  const float4* p = reinterpret_cast<const float4*>(f0 + (size_t)b * Tn + s_base);
  float4 q0 = p[0], q1 = p[1], q2 = p[2], q3 = p[3];
  float fv[16] = {q0.x,q0.y,q0.z,q0.w, q1.x,q1.y,q1.z,q1.w,
                  q2.x,q2.y,q2.z,q2.w, q3.x,q3.y,q3.z,q3.w};

  uint32_t acc = 0u;
#pragma unroll
  for (int j = 0; j < 16; j++) acc += rad0_fx32(fv[j]);

#pragma unroll
  for (int o = 8; o > 0; o >>= 1) acc += __shfl_down_sync(0xffffffffu, acc, o, 16);
  if (sub == 0 && valid) g_pre0[b * NCH + c] = acc;
}

// ---------------- K2: exclusive scan of chunk sums (4 series) --------------
__global__ void k_scan() {
  int s = blockIdx.x;                 // batch
  int lane = threadIdx.x;
  constexpr int PER = (NCH + 31) / 32;   // 59
  uint32_t* row = &g_pre0[(size_t)s * NCH];

  uint32_t v[PER];
  uint32_t tot = 0u;
  int st = lane * PER;
#pragma unroll
  for (int j = 0; j < PER; j++) {
    int c = st + j;
    v[j] = (c < NCH) ? row[c] : 0u;
    tot += v[j];
  }
  uint32_t x = tot;
#pragma unroll
  for (int o = 1; o < 32; o <<= 1) {
    uint32_t y = __shfl_up_sync(0xffffffffu, x, o);
    if (lane >= o) x += y;
  }
  uint32_t run = x - tot;
#pragma unroll
  for (int j = 0; j < PER; j++) {
    int c = st + j;
    if (c < NCH) {
      uint32_t old = v[j];
      row[c] = run;
      run += old;
    }
  }
}

// ---------------- K3: main — phase_h = ri[h] + (h+1)*C0, one IMAD per h ----
__global__ void __launch_bounds__(TPB) k_main(const float* __restrict__ f0,
                                              float* __restrict__ out,
                                              RandIniFx ri, NKey nk) {
  int b = blockIdx.y, c = blockIdx.x;
  int base = c * CHUNK;
  int tid = threadIdx.x;
  int warp = tid >> 5, lane = tid & 31;
  int s0 = tid * SPT;

  __shared__ float so[CHUNK * DIMn];  // 9.2KB staging, natural layout
  __shared__ uint32_t wsum[TPB / 32];

  const float2 a = *reinterpret_cast<const float2*>(f0 + (size_t)b * Tn + base + s0);
  float fv[SPT] = {a.x, a.y};

  // fundamental rads (cached for emit)
  uint32_t r0[SPT] = {rad0_fx32(fv[0]), rad0_fx32(fv[1])};
  uint32_t a0 = r0[0] + r0[1];

  // warp scan (fundamental only)
  uint32_t x = a0;
#pragma unroll
  for (int o = 1; o < 32; o <<= 1) {
    uint32_t y = __shfl_up_sync(0xffffffffu, x, o);
    if (lane >= o) x += y;
  }
  if (lane == 31) wsum[warp] = x;
  uint32_t P = x - a0;                // thread-exclusive within-chunk prefix
  __syncthreads();
#pragma unroll
  for (int w = 0; w < TPB / 32; w++)
    if (w < warp) P += wsum[w];
  P += g_pre0[b * NCH + c];           // + exact cross-chunk fundamental prefix

  // initial phases for this batch (uniform per block; hoisted constants)
  uint32_t riv[DIMn];
#pragma unroll
  for (int h = 0; h < DIMn; h++) riv[h] = ri.v[b * DIMn + h];

  // ---- emit ----
#pragma unroll
  for (int j = 0; j < SPT; j++) {
    float v = fv[j];
    int t = base + s0 + j;
    P += r0[j];                        // inclusive fundamental cumsum
    uint32_t idxbase = ((uint32_t)(b * Tn + t)) * (uint32_t)DIMn;
    float uv  = (v > 0.0f) ? 1.0f : 0.0f;
    float amp = uv * 0.003f + (1.0f - uv) * (0.1f / 3.0f);
    int slot = (s0 + j) * DIMn;
#pragma unroll
    for (int h = 0; h < DIMn; h++) {
      uint32_t p32 = riv[h] + (uint32_t)(h + 1) * P;   // 1 IMAD
      float sw = sine01_full(p32);

      uint32_t bits = rng_bits(nk.k0, nk.k1, idxbase + (uint32_t)h);
      float u = fmaxf(LO_NORMAL, fmaf(bits01(bits), 2.0f, LO_NORMAL));
      float nr = SQRT2F * erfinv_xla(u);

      so[slot + h] = sw * uv + amp * nr;
    }
  }

  __syncthreads();
  // ---- writeout: 4x float4 + 1x float2, coalesced, no index math ----
  size_t outbase = ((size_t)b * Tn + (size_t)base) * (size_t)DIMn;
  {
    const float4* so4 = reinterpret_cast<const float4*>(so);
    float4* out4 = reinterpret_cast<float4*>(out + outbase);
#pragma unroll
    for (int i = 0; i < 4; i++)                       // 4*128 f4 = 2048 floats
      out4[i * TPB + tid] = so4[i * TPB + tid];
    const float2* so2 = reinterpret_cast<const float2*>(so + 2048);
    float2* out2 = reinterpret_cast<float2*>(out + outbase + 2048);
    out2[tid] = so2[tid];                             // last 256 floats
  }
}

// ---------------- host ----------------
extern "C" void kernel_launch(void* const* d_in, const int* in_sizes, int n_in,
                              void* d_out, int out_size) {
  (void)in_sizes; (void)n_in; (void)out_size;
  const float* f0 = (const float*)d_in[0];
  float* out = (float*)d_out;

  uint32_t ik0, ik1, nk0, nk1;
  { uint32_t a, b;
    tf2x32(0u, 42u, 0u, 0u, a, b); ik0 = a; ik1 = b;
    tf2x32(0u, 42u, 0u, 1u, a, b); nk0 = a; nk1 = b; }

  RandIniFx ri;
  for (uint32_t i = 0; i < (uint32_t)(Bn * DIMn); i++) {
    uint32_t bits = rng_bits(ik0, ik1, i);
    float u = bits01(bits);
    if (u < 0.0f) u = 0.0f;
    ri.v[i] = (uint32_t)((double)u * 4294967296.0);  // u mult of 2^-23 -> exact
  }
  for (int b = 0; b < Bn; b++) ri.v[b * DIMn] = 0u;

  NKey nk{nk0, nk1};

  dim3 grid1(K1_GX, Bn);
  k_chunksum0<<<grid1, TPB>>>(f0);
  k_scan<<<Bn, 32>>>();
  dim3 grid3(NCH, Bn);
  k_main<<<grid3, TPB>>>(f0, out, ri, nk);
}

// round 11
// speedup vs baseline: 2.3197x; 1.0850x over previous
#include <cuda_runtime.h>
#include <stdint.h>
#include <math.h>

constexpr int Bn   = 4;
constexpr int Tn   = 480000;
constexpr int DIMn = 9;
constexpr int CHUNK = 256;
constexpr int TPB   = 128;
constexpr int SPT   = CHUNK / TPB;               // 2
constexpr int NCH   = Tn / CHUNK;                // 1875 (exact)
constexpr int K1_CPB = 4;                        // chunks (warps) per K1 block
constexpr int K1_GX  = (NCH + K1_CPB - 1) / K1_CPB;  // 469

constexpr float LO_NORMAL = -0.99999994f;
constexpr float SQRT2F    = 1.41421356237309504880f;
constexpr float RCP48K    = 2.08333333333333333e-05f;  // fl(1/48000)

struct RandIniFx { uint32_t v[Bn * DIMn]; };
struct NKey      { uint32_t k0, k1; };

// per-(b) per-chunk EXACT fundamental phase sums; K2 -> exclusive prefixes
__device__ uint32_t g_pre0[Bn * NCH];

// ---------------- packed f32x2 helpers (sm_103a FFMA2/FMUL2) ----------------
#define PK2(o, lo, hi) \
  asm("mov.b64 %0, {%1, %2};" : "=l"(o) : "r"(__float_as_uint(lo)), "r"(__float_as_uint(hi)))
#define UPK2(lo, hi, in) do { unsigned _l, _h; \
  asm("mov.b64 {%0, %1}, %2;" : "=r"(_l), "=r"(_h) : "l"(in)); \
  (lo) = __uint_as_float(_l); (hi) = __uint_as_float(_h); } while (0)
#define MUL2(o, a, b) \
  asm("mul.rn.f32x2 %0, %1, %2;" : "=l"(o) : "l"(a), "l"(b))
#define FMA2(o, a, b, c) \
  asm("fma.rn.f32x2 %0, %1, %2, %3;" : "=l"(o) : "l"(a), "l"(b), "l"(c))

// ---------------- threefry2x32-20 ----------------
__host__ __device__ __forceinline__ uint32_t rotl32(uint32_t x, int r) {
#ifdef __CUDA_ARCH__
  return __funnelshift_l(x, x, r);
#else
  return (x << r) | (x >> (32 - r));
#endif
}

__host__ __device__ __forceinline__ void tf2x32(uint32_t k0, uint32_t k1,
                                                uint32_t x0, uint32_t x1,
                                                uint32_t& o0, uint32_t& o1) {
  uint32_t k2 = k0 ^ k1 ^ 0x1BD11BDAu;
#define TFR(r) { x0 += x1; x1 = rotl32(x1, (r)); x1 ^= x0; }
  x0 += k0; x1 += k1;
  TFR(13) TFR(15) TFR(26) TFR(6)
  x0 += k1; x1 += k2 + 1u;
  TFR(17) TFR(29) TFR(16) TFR(24)
  x0 += k2; x1 += k0 + 2u;
  TFR(13) TFR(15) TFR(26) TFR(6)
  x0 += k0; x1 += k1 + 3u;
  TFR(17) TFR(29) TFR(16) TFR(24)
  x0 += k1; x1 += k2 + 4u;
  TFR(13) TFR(15) TFR(26) TFR(6)
  x0 += k2; x1 += k0 + 5u;
#undef TFR
  o0 = x0; o1 = x1;
}

__host__ __device__ __forceinline__ uint32_t rng_bits(uint32_t k0, uint32_t k1,
                                                      uint32_t idx) {
  uint32_t a, b;
  tf2x32(k0, k1, 0u, idx, a, b);
  return a ^ b;
}

__host__ __device__ __forceinline__ float bits01(uint32_t bits) {
  union { uint32_t u; float f; } c;
  c.u = (bits >> 9) | 0x3F800000u;
  return c.f - 1.0f;
}

// ---------------- XLA ErfInv32 (fast log; noise error budget ~1e-2) --------
__device__ __forceinline__ float erfinv_xla(float x) {
  float w = -__logf(fmaf(-x, x, 1.0f));
  float p;
  if (w < 5.0f) {
    w = w - 2.5f;
    p =             2.81022636e-08f;
    p = fmaf(p, w,  3.43273939e-07f);
    p = fmaf(p, w, -3.5233877e-06f);
    p = fmaf(p, w, -4.39150654e-06f);
    p = fmaf(p, w,  0.00021858087f);
    p = fmaf(p, w, -0.00125372503f);
    p = fmaf(p, w, -0.00417768164f);
    p = fmaf(p, w,  0.246640727f);
    p = fmaf(p, w,  1.50140941f);
  } else {
    w = sqrtf(w) - 3.0f;
    p =            -0.000200214257f;
    p = fmaf(p, w,  0.000100950558f);
    p = fmaf(p, w,  0.00134934322f);
    p = fmaf(p, w, -0.00367342844f);
    p = fmaf(p, w,  0.00573950773f);
    p = fmaf(p, w, -0.0076224613f);
    p = fmaf(p, w,  0.00943887047f);
    p = fmaf(p, w,  1.00167406f);
    p = fmaf(p, w,  2.83297682f);
  }
  return p * x;
}

// uniform in (-1,1) from bits; fmax(LO,...) dropped: bits01 >= 0 => u >= LO
__device__ __forceinline__ float u_from_bits(uint32_t bits) {
  return fmaf(bits01(bits), 2.0f, LO_NORMAL);
}

// correctly-rounded x/48000 via Markstein (bit-identical to __fdiv_rn)
__device__ __forceinline__ float div48k(float x) {
  float q0 = __fmul_rn(x, RCP48K);
  float e  = fmaf(-48000.0f, q0, x);
  return fmaf(e, RCP48K, q0);
}

// fundamental rad in u32 fixed point, lsb = 2^-32 turns
__device__ __forceinline__ uint32_t rad0_fx32(float f0v) {
  float rad = div48k(f0v);
  return __float2uint_rn(rad * 4294967296.0f);
}

// ---------------- K1: warp-per-chunk fundamental sums ----------------------
__global__ void __launch_bounds__(TPB) k_chunksum0(const float* __restrict__ f0) {
  int b = blockIdx.y;
  int tid = threadIdx.x;
  int warp = tid >> 5, lane = tid & 31;
  int c = blockIdx.x * K1_CPB + warp;
  if (c >= NCH) return;

  const float4* p = reinterpret_cast<const float4*>(
      f0 + (size_t)b * Tn + c * CHUNK + lane * 8);
  float4 q0 = p[0], q1 = p[1];
  uint32_t acc = rad0_fx32(q0.x) + rad0_fx32(q0.y) + rad0_fx32(q0.z) + rad0_fx32(q0.w)
               + rad0_fx32(q1.x) + rad0_fx32(q1.y) + rad0_fx32(q1.z) + rad0_fx32(q1.w);
#pragma unroll
  for (int o = 16; o > 0; o >>= 1) acc += __shfl_down_sync(0xffffffffu, acc, o);
  if (lane == 0) g_pre0[b * NCH + c] = acc;
}

// ---------------- K2: exclusive scan of chunk sums (4 series) --------------
__global__ void k_scan() {
  int s = blockIdx.x;
  int lane = threadIdx.x;
  constexpr int PER = (NCH + 31) / 32;   // 59
  uint32_t* row = &g_pre0[(size_t)s * NCH];

  uint32_t v[PER];
  uint32_t tot = 0u;
  int st = lane * PER;
#pragma unroll
  for (int j = 0; j < PER; j++) {
    int c = st + j;
    v[j] = (c < NCH) ? row[c] : 0u;
    tot += v[j];
  }
  uint32_t x = tot;
#pragma unroll
  for (int o = 1; o < 32; o <<= 1) {
    uint32_t y = __shfl_up_sync(0xffffffffu, x, o);
    if (lane >= o) x += y;
  }
  uint32_t run = x - tot;
#pragma unroll
  for (int j = 0; j < PER; j++) {
    int c = st + j;
    if (c < NCH) {
      uint32_t old = v[j];
      row[c] = run;
      run += old;
    }
  }
}

// ---------------- K3: main — h-loop with j-pair packed in f32x2 ------------
__global__ void __launch_bounds__(TPB) k_main(const float* __restrict__ f0,
                                              float* __restrict__ out,
                                              RandIniFx ri, NKey nk) {
  int b = blockIdx.y, c = blockIdx.x;
  int base = c * CHUNK;
  int tid = threadIdx.x;
  int warp = tid >> 5, lane = tid & 31;
  int s0 = tid * SPT;

  __shared__ float so[CHUNK * DIMn];  // 9.2KB staging, sample-major
  __shared__ uint32_t wsum[TPB / 32];

  const float2 a = *reinterpret_cast<const float2*>(f0 + (size_t)b * Tn + base + s0);
  float fv0 = a.x, fv1 = a.y;

  uint32_t r00 = rad0_fx32(fv0), r01 = rad0_fx32(fv1);
  uint32_t a0 = r00 + r01;

  // warp scan (fundamental only)
  uint32_t x = a0;
#pragma unroll
  for (int o = 1; o < 32; o <<= 1) {
    uint32_t y = __shfl_up_sync(0xffffffffu, x, o);
    if (lane >= o) x += y;
  }
  if (lane == 31) wsum[warp] = x;
  uint32_t P = x - a0;
  __syncthreads();
#pragma unroll
  for (int w = 0; w < TPB / 32; w++)
    if (w < warp) P += wsum[w];
  P += g_pre0[b * NCH + c];

  uint32_t P1 = P + r00;               // inclusive fundamental @ sample j=0
  uint32_t P2 = P1 + r01;              // @ sample j=1

  // per-sample voiced mask / noise amplitude, packed
  float uv0 = (fv0 > 0.0f) ? 1.0f : 0.0f;
  float uv1 = (fv1 > 0.0f) ? 1.0f : 0.0f;
  float am0 = uv0 * 0.003f + (1.0f - uv0) * (0.1f / 3.0f);
  float am1 = uv1 * 0.003f + (1.0f - uv1) * (0.1f / 3.0f);
  unsigned long long uvx, ampx;
  PK2(uvx, uv0, uv1);
  PK2(ampx, am0, am1);

  // packed constants (hoisted; deg-13 odd Taylor of sin)
  unsigned long long Cy, c13, c11, c9, c7, c5, c3, tenth;
  PK2(Cy,   1.46291808e-09f, 1.46291808e-09f);   // 2*pi/2^32
  PK2(c13,  1.60590438e-10f, 1.60590438e-10f);
  PK2(c11, -2.50521084e-08f, -2.50521084e-08f);
  PK2(c9,   2.75573192e-06f, 2.75573192e-06f);
  PK2(c7,  -1.98412698e-04f, -1.98412698e-04f);
  PK2(c5,   8.33333333e-03f, 8.33333333e-03f);
  PK2(c3,  -0.166666667f,   -0.166666667f);
  PK2(tenth, 0.1f, 0.1f);

  uint32_t riv[DIMn];
#pragma unroll
  for (int h = 0; h < DIMn; h++) riv[h] = ri.v[b * DIMn + h];

  uint32_t idxa = ((uint32_t)(b * Tn + base + s0)) * (uint32_t)DIMn;
  int slota = s0 * DIMn;

#pragma unroll
  for (int h = 0; h < DIMn; h++) {
    uint32_t pa = riv[h] + (uint32_t)(h + 1) * P1;
    uint32_t pb = riv[h] + (uint32_t)(h + 1) * P2;

    // packed sine: y = phase * 2pi/2^32; s = sin(y); sw = 0.1*s
    float fa = (float)(int32_t)pa;
    float fb = (float)(int32_t)pb;
    unsigned long long y, y2, q, t, s, sw;
    PK2(y, fa, fb);
    MUL2(y, y, Cy);
    MUL2(y2, y, y);
    q = c13;
    FMA2(q, q, y2, c11);
    FMA2(q, q, y2, c9);
    FMA2(q, q, y2, c7);
    FMA2(q, q, y2, c5);
    FMA2(q, q, y2, c3);
    MUL2(t, y, y2);
    FMA2(s, t, q, y);
    MUL2(sw, s, tenth);

    // noise (scalar threefry + erfinv per sample)
    uint32_t ba = rng_bits(nk.k0, nk.k1, idxa + (uint32_t)h);
    uint32_t bb = rng_bits(nk.k0, nk.k1, idxa + 9u + (uint32_t)h);
    float na = SQRT2F * erfinv_xla(u_from_bits(ba));
    float nb = SQRT2F * erfinv_xla(u_from_bits(bb));
    unsigned long long nx, swu, ox;
    PK2(nx, na, nb);
    MUL2(swu, sw, uvx);
    FMA2(ox, ampx, nx, swu);
    float oa, ob;
    UPK2(oa, ob, ox);
    so[slota + h] = oa;
    so[slota + DIMn + h] = ob;
  }

  __syncthreads();
  // ---- writeout: 4x float4 + 1x float2, coalesced ----
  size_t outbase = ((size_t)b * Tn + (size_t)base) * (size_t)DIMn;
  {
    const float4* so4 = reinterpret_cast<const float4*>(so);
    float4* out4 = reinterpret_cast<float4*>(out + outbase);
#pragma unroll
    for (int i = 0; i < 4; i++)
      out4[i * TPB + tid] = so4[i * TPB + tid];
    const float2* so2 = reinterpret_cast<const float2*>(so + 2048);
    float2* out2 = reinterpret_cast<float2*>(out + outbase + 2048);
    out2[tid] = so2[tid];
  }
}

// ---------------- host ----------------
extern "C" void kernel_launch(void* const* d_in, const int* in_sizes, int n_in,
                              void* d_out, int out_size) {
  (void)in_sizes; (void)n_in; (void)out_size;
  const float* f0 = (const float*)d_in[0];
  float* out = (float*)d_out;

  uint32_t ik0, ik1, nk0, nk1;
  { uint32_t a, b;
    tf2x32(0u, 42u, 0u, 0u, a, b); ik0 = a; ik1 = b;
    tf2x32(0u, 42u, 0u, 1u, a, b); nk0 = a; nk1 = b; }

  RandIniFx ri;
  for (uint32_t i = 0; i < (uint32_t)(Bn * DIMn); i++) {
    uint32_t bits = rng_bits(ik0, ik1, i);
    float u = bits01(bits);
    if (u < 0.0f) u = 0.0f;
    ri.v[i] = (uint32_t)((double)u * 4294967296.0);  // u mult of 2^-23 -> exact
  }
  for (int b = 0; b < Bn; b++) ri.v[b * DIMn] = 0u;

  NKey nk{nk0, nk1};

  dim3 grid1(K1_GX, Bn);
  k_chunksum0<<<grid1, TPB>>>(f0);
  k_scan<<<Bn, 32>>>();
  dim3 grid3(NCH, Bn);
  k_main<<<grid3, TPB>>>(f0, out, ri, nk);
}

// round 13
// speedup vs baseline: 2.5435x; 1.0965x over previous
#include <cuda_runtime.h>
#include <stdint.h>
#include <math.h>

constexpr int Bn   = 4;
constexpr int Tn   = 480000;
constexpr int DIMn = 9;
constexpr int CHUNK = 256;
constexpr int TPB   = 128;
constexpr int SPT   = CHUNK / TPB;               // 2
constexpr int NCH   = Tn / CHUNK;                // 1875 (exact)
constexpr int K1_CPB = 4;                        // chunks (warps) per K1 block
constexpr int K1_GX  = (NCH + K1_CPB - 1) / K1_CPB;  // 469

constexpr float LO_NORMAL = -0.99999994f;
constexpr float SQRT2F    = 1.41421356237309504880f;
constexpr float RCP48K    = 2.08333333333333333e-05f;  // fl(1/48000)

struct RandIniFx { uint32_t v[Bn * DIMn]; };
struct NKey      { uint32_t k0, k1; };

// per-(b) per-chunk EXACT fundamental phase sums; K2 -> exclusive prefixes
__device__ uint32_t g_pre0[Bn * NCH];

// ---------------- packed f32x2 helpers (sm_103a FFMA2/FMUL2) ----------------
#define PK2(o, lo, hi) \
  asm("mov.b64 %0, {%1, %2};" : "=l"(o) : "r"(__float_as_uint(lo)), "r"(__float_as_uint(hi)))
#define UPK2(lo, hi, in) do { unsigned _l, _h; \
  asm("mov.b64 {%0, %1}, %2;" : "=r"(_l), "=r"(_h) : "l"(in)); \
  (lo) = __uint_as_float(_l); (hi) = __uint_as_float(_h); } while (0)
#define MUL2(o, a, b) \
  asm("mul.rn.f32x2 %0, %1, %2;" : "=l"(o) : "l"(a), "l"(b))
#define ADD2(o, a, b) \
  asm("add.rn.f32x2 %0, %1, %2;" : "=l"(o) : "l"(a), "l"(b))
#define FMA2(o, a, b, c) \
  asm("fma.rn.f32x2 %0, %1, %2, %3;" : "=l"(o) : "l"(a), "l"(b), "l"(c))

// ---------------- threefry2x32-20 ----------------
__host__ __device__ __forceinline__ uint32_t rotl32(uint32_t x, int r) {
#ifdef __CUDA_ARCH__
  return __funnelshift_l(x, x, r);
#else
  return (x << r) | (x >> (32 - r));
#endif
}

__host__ __device__ __forceinline__ void tf2x32(uint32_t k0, uint32_t k1,
                                                uint32_t x0, uint32_t x1,
                                                uint32_t& o0, uint32_t& o1) {
  uint32_t k2 = k0 ^ k1 ^ 0x1BD11BDAu;
#define TFR(r) { x0 += x1; x1 = rotl32(x1, (r)); x1 ^= x0; }
  x0 += k0; x1 += k1;
  TFR(13) TFR(15) TFR(26) TFR(6)
  x0 += k1; x1 += k2 + 1u;
  TFR(17) TFR(29) TFR(16) TFR(24)
  x0 += k2; x1 += k0 + 2u;
  TFR(13) TFR(15) TFR(26) TFR(6)
  x0 += k0; x1 += k1 + 3u;
  TFR(17) TFR(29) TFR(16) TFR(24)
  x0 += k1; x1 += k2 + 4u;
  TFR(13) TFR(15) TFR(26) TFR(6)
  x0 += k2; x1 += k0 + 5u;
#undef TFR
  o0 = x0; o1 = x1;
}

__host__ __device__ __forceinline__ uint32_t rng_bits(uint32_t k0, uint32_t k1,
                                                      uint32_t idx) {
  uint32_t a, b;
  tf2x32(k0, k1, 0u, idx, a, b);
  return a ^ b;
}

__host__ __device__ __forceinline__ float bits01(uint32_t bits) {
  union { uint32_t u; float f; } c;
  c.u = (bits >> 9) | 0x3F800000u;
  return c.f - 1.0f;
}

// scalar erfinv tail given x and w = -ln(1-x^2) (rare-divergence path)
__device__ __noinline__ float erfinv_from_w(float x, float w) {
  float p;
  if (w < 5.0f) {
    w = w - 2.5f;
    p =             2.81022636e-08f;
    p = fmaf(p, w,  3.43273939e-07f);
    p = fmaf(p, w, -3.5233877e-06f);
    p = fmaf(p, w, -4.39150654e-06f);
    p = fmaf(p, w,  0.00021858087f);
    p = fmaf(p, w, -0.00125372503f);
    p = fmaf(p, w, -0.00417768164f);
    p = fmaf(p, w,  0.246640727f);
    p = fmaf(p, w,  1.50140941f);
  } else {
    w = sqrtf(w) - 3.0f;
    p =            -0.000200214257f;
    p = fmaf(p, w,  0.000100950558f);
    p = fmaf(p, w,  0.00134934322f);
    p = fmaf(p, w, -0.00367342844f);
    p = fmaf(p, w,  0.00573950773f);
    p = fmaf(p, w, -0.0076224613f);
    p = fmaf(p, w,  0.00943887047f);
    p = fmaf(p, w,  1.00167406f);
    p = fmaf(p, w,  2.83297682f);
  }
  return p * x;
}

// correctly-rounded x/48000 via Markstein (bit-identical to __fdiv_rn)
__device__ __forceinline__ float div48k(float x) {
  float q0 = __fmul_rn(x, RCP48K);
  float e  = fmaf(-48000.0f, q0, x);
  return fmaf(e, RCP48K, q0);
}

// fundamental rad in u32 fixed point, lsb = 2^-32 turns
__device__ __forceinline__ uint32_t rad0_fx32(float f0v) {
  float rad = div48k(f0v);
  return __float2uint_rn(rad * 4294967296.0f);
}

// ---------------- K1: warp-per-chunk fundamental sums ----------------------
__global__ void __launch_bounds__(TPB) k_chunksum0(const float* __restrict__ f0) {
  int b = blockIdx.y;
  int tid = threadIdx.x;
  int warp = tid >> 5, lane = tid & 31;
  int c = blockIdx.x * K1_CPB + warp;
  if (c >= NCH) return;

  const float4* p = reinterpret_cast<const float4*>(
      f0 + (size_t)b * Tn + c * CHUNK + lane * 8);
  float4 q0 = p[0], q1 = p[1];
  uint32_t acc = rad0_fx32(q0.x) + rad0_fx32(q0.y) + rad0_fx32(q0.z) + rad0_fx32(q0.w)
               + rad0_fx32(q1.x) + rad0_fx32(q1.y) + rad0_fx32(q1.z) + rad0_fx32(q1.w);
#pragma unroll
  for (int o = 16; o > 0; o >>= 1) acc += __shfl_down_sync(0xffffffffu, acc, o);
  if (lane == 0) g_pre0[b * NCH + c] = acc;
}

// ---------------- K2: exclusive scan of chunk sums (4 series) --------------
__global__ void k_scan() {
  int s = blockIdx.x;
  int lane = threadIdx.x;
  constexpr int PER = (NCH + 31) / 32;   // 59
  uint32_t* row = &g_pre0[(size_t)s * NCH];

  uint32_t v[PER];
  uint32_t tot = 0u;
  int st = lane * PER;
#pragma unroll
  for (int j = 0; j < PER; j++) {
    int c = st + j;
    v[j] = (c < NCH) ? row[c] : 0u;
    tot += v[j];
  }
  uint32_t x = tot;
#pragma unroll
  for (int o = 1; o < 32; o <<= 1) {
    uint32_t y = __shfl_up_sync(0xffffffffu, x, o);
    if (lane >= o) x += y;
  }
  uint32_t run = x - tot;
#pragma unroll
  for (int j = 0; j < PER; j++) {
    int c = st + j;
    if (c < NCH) {
      uint32_t old = v[j];
      row[c] = run;
      run += old;
    }
  }
}

// ---------------- K3: main — packed sine AND packed erfinv -----------------
__global__ void __launch_bounds__(TPB) k_main(const float* __restrict__ f0,
                                              float* __restrict__ out,
                                              RandIniFx ri, NKey nk) {
  int b = blockIdx.y, c = blockIdx.x;
  int base = c * CHUNK;
  int tid = threadIdx.x;
  int warp = tid >> 5, lane = tid & 31;
  int s0 = tid * SPT;

  __shared__ float so[CHUNK * DIMn];  // 9.2KB staging, sample-major
  __shared__ uint32_t wsum[TPB / 32];

  const float2 a = *reinterpret_cast<const float2*>(f0 + (size_t)b * Tn + base + s0);
  float fv0 = a.x, fv1 = a.y;

  uint32_t r00 = rad0_fx32(fv0), r01 = rad0_fx32(fv1);
  uint32_t a0 = r00 + r01;

  // warp scan (fundamental only)
  uint32_t x = a0;
#pragma unroll
  for (int o = 1; o < 32; o <<= 1) {
    uint32_t y = __shfl_up_sync(0xffffffffu, x, o);
    if (lane >= o) x += y;
  }
  if (lane == 31) wsum[warp] = x;
  uint32_t P = x - a0;
  __syncthreads();
#pragma unroll
  for (int w = 0; w < TPB / 32; w++)
    if (w < warp) P += wsum[w];
  P += g_pre0[b * NCH + c];

  uint32_t P1 = P + r00;               // inclusive fundamental @ sample j=0
  uint32_t P2 = P1 + r01;              // @ sample j=1

  // per-sample voiced mask / noise amplitude (sqrt2 folded in), packed
  float uv0 = (fv0 > 0.0f) ? 1.0f : 0.0f;
  float uv1 = (fv1 > 0.0f) ? 1.0f : 0.0f;
  float am0 = (uv0 * 0.003f + (1.0f - uv0) * (0.1f / 3.0f)) * SQRT2F;
  float am1 = (uv1 * 0.003f + (1.0f - uv1) * (0.1f / 3.0f)) * SQRT2F;
  unsigned long long uvx, ampx;
  PK2(uvx, uv0, uv1);
  PK2(ampx, am0, am1);

  // packed constants
  unsigned long long Cy, s13, s11, s9, s7, s5, s3, tenth;
  PK2(Cy,   1.46291808e-09f, 1.46291808e-09f);   // 2*pi/2^32
  PK2(s13,  1.60590438e-10f, 1.60590438e-10f);
  PK2(s11, -2.50521084e-08f, -2.50521084e-08f);
  PK2(s9,   2.75573192e-06f, 2.75573192e-06f);
  PK2(s7,  -1.98412698e-04f, -1.98412698e-04f);
  PK2(s5,   8.33333333e-03f, 8.33333333e-03f);
  PK2(s3,  -0.166666667f,   -0.166666667f);
  PK2(tenth, 0.1f, 0.1f);
  unsigned long long two2, lo2, one2, mone2, mln2, m2p5;
  PK2(two2,  2.0f, 2.0f);
  PK2(lo2,   LO_NORMAL, LO_NORMAL);     // exact reference addend
  PK2(one2,  1.0f, 1.0f);
  PK2(mone2,-1.0f,-1.0f);
  PK2(mln2, -0.693147181f, -0.693147181f);
  PK2(m2p5, -2.5f, -2.5f);
  unsigned long long e8,e7,e6,e5,e4,e3,e2,e1,e0;
  PK2(e8,  2.81022636e-08f,  2.81022636e-08f);
  PK2(e7,  3.43273939e-07f,  3.43273939e-07f);
  PK2(e6, -3.5233877e-06f,  -3.5233877e-06f);
  PK2(e5, -4.39150654e-06f, -4.39150654e-06f);
  PK2(e4,  0.00021858087f,   0.00021858087f);
  PK2(e3, -0.00125372503f,  -0.00125372503f);
  PK2(e2, -0.00417768164f,  -0.00417768164f);
  PK2(e1,  0.246640727f,     0.246640727f);
  PK2(e0,  1.50140941f,      1.50140941f);

  uint32_t riv[DIMn];
#pragma unroll
  for (int h = 0; h < DIMn; h++) riv[h] = ri.v[b * DIMn + h];

  uint32_t idxa = ((uint32_t)(b * Tn + base + s0)) * (uint32_t)DIMn;
  int slota = s0 * DIMn;

#pragma unroll
  for (int h = 0; h < DIMn; h++) {
    uint32_t pa = riv[h] + (uint32_t)(h + 1) * P1;
    uint32_t pb = riv[h] + (uint32_t)(h + 1) * P2;

    // ---- packed sine: sw = 0.1*sin(phase * 2pi/2^32) ----
    float fa = (float)(int32_t)pa;
    float fb = (float)(int32_t)pb;
    unsigned long long y, y2, q, t, s, sw;
    PK2(y, fa, fb);
    MUL2(y, y, Cy);
    MUL2(y2, y, y);
    q = s13;
    FMA2(q, q, y2, s11);
    FMA2(q, q, y2, s9);
    FMA2(q, q, y2, s7);
    FMA2(q, q, y2, s5);
    FMA2(q, q, y2, s3);
    MUL2(t, y, y2);
    FMA2(s, t, q, y);
    MUL2(sw, s, tenth);

    // ---- packed noise: b01 = f-1 (exact); u = fma(b01,2,LO) as in ref ----
    uint32_t ba = rng_bits(nk.k0, nk.k1, idxa + (uint32_t)h);
    uint32_t bb = rng_bits(nk.k0, nk.k1, idxa + 9u + (uint32_t)h);
    float fra = __uint_as_float((ba >> 9) | 0x3F800000u);
    float frb = __uint_as_float((bb >> 9) | 0x3F800000u);
    unsigned long long fx, bx, ux, xx, vx, wx, nx;
    PK2(fx, fra, frb);
    ADD2(bx, fx, mone2);               // f - 1  (Sterbenz-exact, >= 0)
    FMA2(ux, bx, two2, lo2);           // u in [LO_NORMAL, 1-2^-24] — never ±1
    MUL2(xx, ux, ux);
    FMA2(vx, xx, mone2, one2);         // 1 - u^2 > 0 on this range
    float va, vb;
    UPK2(va, vb, vx);
    float la = __log2f(va), lb = __log2f(vb);   // MUFU pipe
    unsigned long long lg;
    PK2(lg, la, lb);
    MUL2(wx, lg, mln2);                // w = -ln(1-u^2)
    float wa, wb;
    UPK2(wa, wb, wx);
    if (wa < 5.0f && wb < 5.0f) {      // common path: ~99.3% per lane
      unsigned long long ws, pq;
      ADD2(ws, wx, m2p5);
      pq = e8;
      FMA2(pq, pq, ws, e7);
      FMA2(pq, pq, ws, e6);
      FMA2(pq, pq, ws, e5);
      FMA2(pq, pq, ws, e4);
      FMA2(pq, pq, ws, e3);
      FMA2(pq, pq, ws, e2);
      FMA2(pq, pq, ws, e1);
      FMA2(pq, pq, ws, e0);
      MUL2(nx, pq, ux);
    } else {                           // rare tail: scalar both lanes
      float xa, xb;
      UPK2(xa, xb, ux);
      float na = erfinv_from_w(xa, wa);
      float nb = erfinv_from_w(xb, wb);
      PK2(nx, na, nb);
    }

    unsigned long long swu, ox;
    MUL2(swu, sw, uvx);
    FMA2(ox, ampx, nx, swu);           // ampx includes sqrt2
    float oa, ob;
    UPK2(oa, ob, ox);
    so[slota + h] = oa;
    so[slota + DIMn + h] = ob;
  }

  __syncthreads();
  // ---- writeout: 4x float4 + 1x float2, coalesced ----
  size_t outbase = ((size_t)b * Tn + (size_t)base) * (size_t)DIMn;
  {
    const float4* so4 = reinterpret_cast<const float4*>(so);
    float4* out4 = reinterpret_cast<float4*>(out + outbase);
#pragma unroll
    for (int i = 0; i < 4; i++)
      out4[i * TPB + tid] = so4[i * TPB + tid];
    const float2* so2 = reinterpret_cast<const float2*>(so + 2048);
    float2* out2 = reinterpret_cast<float2*>(out + outbase + 2048);
    out2[tid] = so2[tid];
  }
}

// ---------------- host ----------------
extern "C" void kernel_launch(void* const* d_in, const int* in_sizes, int n_in,
                              void* d_out, int out_size) {
  (void)in_sizes; (void)n_in; (void)out_size;
  const float* f0 = (const float*)d_in[0];
  float* out = (float*)d_out;

  uint32_t ik0, ik1, nk0, nk1;
  { uint32_t a, b;
    tf2x32(0u, 42u, 0u, 0u, a, b); ik0 = a; ik1 = b;
    tf2x32(0u, 42u, 0u, 1u, a, b); nk0 = a; nk1 = b; }

  RandIniFx ri;
  for (uint32_t i = 0; i < (uint32_t)(Bn * DIMn); i++) {
    uint32_t bits = rng_bits(ik0, ik1, i);
    float u = bits01(bits);
    if (u < 0.0f) u = 0.0f;
    ri.v[i] = (uint32_t)((double)u * 4294967296.0);  // u mult of 2^-23 -> exact
  }
  for (int b = 0; b < Bn; b++) ri.v[b * DIMn] = 0u;

  NKey nk{nk0, nk1};

  dim3 grid1(K1_GX, Bn);
  k_chunksum0<<<grid1, TPB>>>(f0);
  k_scan<<<Bn, 32>>>();
  dim3 grid3(NCH, Bn);
  k_main<<<grid3, TPB>>>(f0, out, ri, nk);
}

// round 14
// speedup vs baseline: 2.6064x; 1.0247x over previous
#include <cuda_runtime.h>
#include <stdint.h>
#include <math.h>

constexpr int Bn   = 4;
constexpr int Tn   = 480000;
constexpr int DIMn = 9;
constexpr int CHUNK = 256;
constexpr int TPB   = 128;
constexpr int SPT   = CHUNK / TPB;               // 2
constexpr int NCH   = Tn / CHUNK;                // 1875 (exact)
constexpr int K1_CPB = 4;                        // chunks (warps) per K1 block
constexpr int K1_GX  = (NCH + K1_CPB - 1) / K1_CPB;  // 469

constexpr float LO_NORMAL = -0.99999994f;
constexpr float SQRT2F    = 1.41421356237309504880f;
constexpr float RCP48K    = 2.08333333333333333e-05f;  // fl(1/48000)
constexpr float EXP_M5    = 6.73794700e-03f;           // e^-5 (fast-path bound)

struct RandIniFx { uint32_t v[Bn * DIMn]; };
struct NKey      { uint32_t k0, k1; };

// per-(b) per-chunk EXACT fundamental phase sums; K2 -> exclusive prefixes
__device__ uint32_t g_pre0[Bn * NCH];

// ---------------- packed f32x2 helpers (sm_103a FFMA2/FMUL2) ----------------
#define PK2(o, lo, hi) \
  asm("mov.b64 %0, {%1, %2};" : "=l"(o) : "r"(__float_as_uint(lo)), "r"(__float_as_uint(hi)))
#define UPK2(lo, hi, in) do { unsigned _l, _h; \
  asm("mov.b64 {%0, %1}, %2;" : "=r"(_l), "=r"(_h) : "l"(in)); \
  (lo) = __uint_as_float(_l); (hi) = __uint_as_float(_h); } while (0)
#define MUL2(o, a, b) \
  asm("mul.rn.f32x2 %0, %1, %2;" : "=l"(o) : "l"(a), "l"(b))
#define ADD2(o, a, b) \
  asm("add.rn.f32x2 %0, %1, %2;" : "=l"(o) : "l"(a), "l"(b))
#define FMA2(o, a, b, c) \
  asm("fma.rn.f32x2 %0, %1, %2, %3;" : "=l"(o) : "l"(a), "l"(b), "l"(c))

// ---------------- threefry2x32-20 ----------------
__host__ __device__ __forceinline__ uint32_t rotl32(uint32_t x, int r) {
#ifdef __CUDA_ARCH__
  return __funnelshift_l(x, x, r);
#else
  return (x << r) | (x >> (32 - r));
#endif
}

__host__ __device__ __forceinline__ void tf2x32(uint32_t k0, uint32_t k1,
                                                uint32_t x0, uint32_t x1,
                                                uint32_t& o0, uint32_t& o1) {
  uint32_t k2 = k0 ^ k1 ^ 0x1BD11BDAu;
#define TFR(r) { x0 += x1; x1 = rotl32(x1, (r)); x1 ^= x0; }
  x0 += k0; x1 += k1;
  TFR(13) TFR(15) TFR(26) TFR(6)
  x0 += k1; x1 += k2 + 1u;
  TFR(17) TFR(29) TFR(16) TFR(24)
  x0 += k2; x1 += k0 + 2u;
  TFR(13) TFR(15) TFR(26) TFR(6)
  x0 += k0; x1 += k1 + 3u;
  TFR(17) TFR(29) TFR(16) TFR(24)
  x0 += k1; x1 += k2 + 4u;
  TFR(13) TFR(15) TFR(26) TFR(6)
  x0 += k2; x1 += k0 + 5u;
#undef TFR
  o0 = x0; o1 = x1;
}

__host__ __device__ __forceinline__ uint32_t rng_bits(uint32_t k0, uint32_t k1,
                                                      uint32_t idx) {
  uint32_t a, b;
  tf2x32(k0, k1, 0u, idx, a, b);
  return a ^ b;
}

__host__ __device__ __forceinline__ float bits01(uint32_t bits) {
  union { uint32_t u; float f; } c;
  c.u = (bits >> 9) | 0x3F800000u;
  return c.f - 1.0f;
}

// scalar erfinv tail given x and w = -ln(1-x^2) (rare-divergence path)
__device__ __noinline__ float erfinv_from_w(float x, float w) {
  float p;
  if (w < 5.0f) {
    w = w - 2.5f;
    p =             2.81022636e-08f;
    p = fmaf(p, w,  3.43273939e-07f);
    p = fmaf(p, w, -3.5233877e-06f);
    p = fmaf(p, w, -4.39150654e-06f);
    p = fmaf(p, w,  0.00021858087f);
    p = fmaf(p, w, -0.00125372503f);
    p = fmaf(p, w, -0.00417768164f);
    p = fmaf(p, w,  0.246640727f);
    p = fmaf(p, w,  1.50140941f);
  } else {
    w = sqrtf(w) - 3.0f;
    p =            -0.000200214257f;
    p = fmaf(p, w,  0.000100950558f);
    p = fmaf(p, w,  0.00134934322f);
    p = fmaf(p, w, -0.00367342844f);
    p = fmaf(p, w,  0.00573950773f);
    p = fmaf(p, w, -0.0076224613f);
    p = fmaf(p, w,  0.00943887047f);
    p = fmaf(p, w,  1.00167406f);
    p = fmaf(p, w,  2.83297682f);
  }
  return p * x;
}

// correctly-rounded x/48000 via Markstein (bit-identical to __fdiv_rn)
__device__ __forceinline__ float div48k(float x) {
  float q0 = __fmul_rn(x, RCP48K);
  float e  = fmaf(-48000.0f, q0, x);
  return fmaf(e, RCP48K, q0);
}

// fundamental rad in u32 fixed point, lsb = 2^-32 turns
__device__ __forceinline__ uint32_t rad0_fx32(float f0v) {
  float rad = div48k(f0v);
  return __float2uint_rn(rad * 4294967296.0f);
}

// ---------------- K1: warp-per-chunk fundamental sums ----------------------
__global__ void __launch_bounds__(TPB) k_chunksum0(const float* __restrict__ f0) {
  int b = blockIdx.y;
  int tid = threadIdx.x;
  int warp = tid >> 5, lane = tid & 31;
  int c = blockIdx.x * K1_CPB + warp;
  if (c >= NCH) return;

  const float4* p = reinterpret_cast<const float4*>(
      f0 + (size_t)b * Tn + c * CHUNK + lane * 8);
  float4 q0 = p[0], q1 = p[1];
  uint32_t acc = rad0_fx32(q0.x) + rad0_fx32(q0.y) + rad0_fx32(q0.z) + rad0_fx32(q0.w)
               + rad0_fx32(q1.x) + rad0_fx32(q1.y) + rad0_fx32(q1.z) + rad0_fx32(q1.w);
#pragma unroll
  for (int o = 16; o > 0; o >>= 1) acc += __shfl_down_sync(0xffffffffu, acc, o);
  if (lane == 0) g_pre0[b * NCH + c] = acc;
}

// ---------------- K2: exclusive scan of chunk sums (4 series) --------------
__global__ void k_scan() {
  int s = blockIdx.x;
  int lane = threadIdx.x;
  constexpr int PER = (NCH + 31) / 32;   // 59
  uint32_t* row = &g_pre0[(size_t)s * NCH];

  uint32_t v[PER];
  uint32_t tot = 0u;
  int st = lane * PER;
#pragma unroll
  for (int j = 0; j < PER; j++) {
    int c = st + j;
    v[j] = (c < NCH) ? row[c] : 0u;
    tot += v[j];
  }
  uint32_t x = tot;
#pragma unroll
  for (int o = 1; o < 32; o <<= 1) {
    uint32_t y = __shfl_up_sync(0xffffffffu, x, o);
    if (lane >= o) x += y;
  }
  uint32_t run = x - tot;
#pragma unroll
  for (int j = 0; j < PER; j++) {
    int c = st + j;
    if (c < NCH) {
      uint32_t old = v[j];
      row[c] = run;
      run += old;
    }
  }
}

// ---------------- K3: main — MUFU sine + packed erfinv ---------------------
__global__ void __launch_bounds__(TPB) k_main(const float* __restrict__ f0,
                                              float* __restrict__ out,
                                              RandIniFx ri, NKey nk) {
  int b = blockIdx.y, c = blockIdx.x;
  int base = c * CHUNK;
  int tid = threadIdx.x;
  int warp = tid >> 5, lane = tid & 31;
  int s0 = tid * SPT;

  __shared__ float so[CHUNK * DIMn];  // 9.2KB staging, sample-major
  __shared__ uint32_t wsum[TPB / 32];

  const float2 a = *reinterpret_cast<const float2*>(f0 + (size_t)b * Tn + base + s0);
  float fv0 = a.x, fv1 = a.y;

  uint32_t r00 = rad0_fx32(fv0), r01 = rad0_fx32(fv1);
  uint32_t a0 = r00 + r01;

  // warp scan (fundamental only)
  uint32_t x = a0;
#pragma unroll
  for (int o = 1; o < 32; o <<= 1) {
    uint32_t y = __shfl_up_sync(0xffffffffu, x, o);
    if (lane >= o) x += y;
  }
  if (lane == 31) wsum[warp] = x;
  uint32_t P = x - a0;
  __syncthreads();
#pragma unroll
  for (int w = 0; w < TPB / 32; w++)
    if (w < warp) P += wsum[w];
  P += g_pre0[b * NCH + c];

  uint32_t P1 = P + r00;               // inclusive fundamental @ sample j=0
  uint32_t P2 = P1 + r01;              // @ sample j=1

  // per-sample voiced mask (0.1 folded) / noise amplitude (sqrt2 folded)
  float uv0 = (fv0 > 0.0f) ? 1.0f : 0.0f;
  float uv1 = (fv1 > 0.0f) ? 1.0f : 0.0f;
  float am0 = (uv0 * 0.003f + (1.0f - uv0) * (0.1f / 3.0f)) * SQRT2F;
  float am1 = (uv1 * 0.003f + (1.0f - uv1) * (0.1f / 3.0f)) * SQRT2F;
  unsigned long long uvx, ampx;
  PK2(uvx, uv0 * 0.1f, uv1 * 0.1f);    // 0.1*uv: scales raw sin directly
  PK2(ampx, am0, am1);

  // packed constants
  unsigned long long two2, lo2, one2, mone2, mln2_m25;
  PK2(two2,  2.0f, 2.0f);
  PK2(lo2,   LO_NORMAL, LO_NORMAL);
  PK2(one2,  1.0f, 1.0f);
  PK2(mone2,-1.0f,-1.0f);
  // ws = lg * (-ln2) + (-2.5)  — one FMA2
  unsigned long long mln2x, m2p5x;
  PK2(mln2x, -0.693147181f, -0.693147181f);
  PK2(m2p5x, -2.5f, -2.5f);
  (void)mln2_m25;
  unsigned long long e8,e7,e6,e5,e4,e3,e2,e1,e0;
  PK2(e8,  2.81022636e-08f,  2.81022636e-08f);
  PK2(e7,  3.43273939e-07f,  3.43273939e-07f);
  PK2(e6, -3.5233877e-06f,  -3.5233877e-06f);
  PK2(e5, -4.39150654e-06f, -4.39150654e-06f);
  PK2(e4,  0.00021858087f,   0.00021858087f);
  PK2(e3, -0.00125372503f,  -0.00125372503f);
  PK2(e2, -0.00417768164f,  -0.00417768164f);
  PK2(e1,  0.246640727f,     0.246640727f);
  PK2(e0,  1.50140941f,      1.50140941f);

  uint32_t riv[DIMn];
#pragma unroll
  for (int h = 0; h < DIMn; h++) riv[h] = ri.v[b * DIMn + h];

  uint32_t idxa = ((uint32_t)(b * Tn + base + s0)) * (uint32_t)DIMn;
  int slota = s0 * DIMn;
  const float C2PI = 1.46291807926715968e-09f;   // 2*pi/2^32

#pragma unroll
  for (int h = 0; h < DIMn; h++) {
    uint32_t pa = riv[h] + (uint32_t)(h + 1) * P1;
    uint32_t pb = riv[h] + (uint32_t)(h + 1) * P2;

    // ---- sine via MUFU (abs err ~2^-21, budget 1e-4): sin(phase*2pi/2^32)
    float sa = __sinf((float)(int32_t)pa * C2PI);
    float sb = __sinf((float)(int32_t)pb * C2PI);
    unsigned long long sx;
    PK2(sx, sa, sb);

    // ---- packed noise: b01 = f-1 (exact); u = fma(b01,2,LO) as in ref ----
    uint32_t ba = rng_bits(nk.k0, nk.k1, idxa + (uint32_t)h);
    uint32_t bb = rng_bits(nk.k0, nk.k1, idxa + 9u + (uint32_t)h);
    float fra = __uint_as_float((ba >> 9) | 0x3F800000u);
    float frb = __uint_as_float((bb >> 9) | 0x3F800000u);
    unsigned long long fx, bx, ux, xx, vx, nx;
    PK2(fx, fra, frb);
    ADD2(bx, fx, mone2);               // f - 1  (Sterbenz-exact, >= 0)
    FMA2(ux, bx, two2, lo2);           // u in [LO_NORMAL, 1-2^-24] — never ±1
    MUL2(xx, ux, ux);
    FMA2(vx, xx, mone2, one2);         // 1 - u^2 > 0
    float va, vb;
    UPK2(va, vb, vx);
    float la = __log2f(va), lb = __log2f(vb);   // MUFU pipe
    unsigned long long lg;
    PK2(lg, la, lb);
    // fast path iff both w < 5  <=>  both v > e^-5 (boundary slop harmless:
    // the scalar fallback re-derives the branch from the same w)
    if (fminf(va, vb) > EXP_M5) {
      unsigned long long ws, pq;
      FMA2(ws, lg, mln2x, m2p5x);      // w - 2.5 in one op
      pq = e8;
      FMA2(pq, pq, ws, e7);
      FMA2(pq, pq, ws, e6);
      FMA2(pq, pq, ws, e5);
      FMA2(pq, pq, ws, e4);
      FMA2(pq, pq, ws, e3);
      FMA2(pq, pq, ws, e2);
      FMA2(pq, pq, ws, e1);
      FMA2(pq, pq, ws, e0);
      MUL2(nx, pq, ux);
    } else {                           // rare tail: scalar both lanes
      float xa, xb;
      UPK2(xa, xb, ux);
      float wa = la * -0.693147181f;
      float wb = lb * -0.693147181f;
      float na = erfinv_from_w(xa, wa);
      float nb = erfinv_from_w(xb, wb);
      PK2(nx, na, nb);
    }

    unsigned long long swu, ox;
    MUL2(swu, sx, uvx);                // sin * (0.1*uv)
    FMA2(ox, ampx, nx, swu);           // ampx includes sqrt2
    float oa, ob;
    UPK2(oa, ob, ox);
    so[slota + h] = oa;
    so[slota + DIMn + h] = ob;
  }

  __syncthreads();
  // ---- writeout: 4x float4 + 1x float2, coalesced ----
  size_t outbase = ((size_t)b * Tn + (size_t)base) * (size_t)DIMn;
  {
    const float4* so4 = reinterpret_cast<const float4*>(so);
    float4* out4 = reinterpret_cast<float4*>(out + outbase);
#pragma unroll
    for (int i = 0; i < 4; i++)
      out4[i * TPB + tid] = so4[i * TPB + tid];
    const float2* so2 = reinterpret_cast<const float2*>(so + 2048);
    float2* out2 = reinterpret_cast<float2*>(out + outbase + 2048);
    out2[tid] = so2[tid];
  }
}

// ---------------- host ----------------
extern "C" void kernel_launch(void* const* d_in, const int* in_sizes, int n_in,
                              void* d_out, int out_size) {
  (void)in_sizes; (void)n_in; (void)out_size;
  const float* f0 = (const float*)d_in[0];
  float* out = (float*)d_out;

  uint32_t ik0, ik1, nk0, nk1;
  { uint32_t a, b;
    tf2x32(0u, 42u, 0u, 0u, a, b); ik0 = a; ik1 = b;
    tf2x32(0u, 42u, 0u, 1u, a, b); nk0 = a; nk1 = b; }

  RandIniFx ri;
  for (uint32_t i = 0; i < (uint32_t)(Bn * DIMn); i++) {
    uint32_t bits = rng_bits(ik0, ik1, i);
    float u = bits01(bits);
    if (u < 0.0f) u = 0.0f;
    ri.v[i] = (uint32_t)((double)u * 4294967296.0);  // u mult of 2^-23 -> exact
  }
  for (int b = 0; b < Bn; b++) ri.v[b * DIMn] = 0u;

  NKey nk{nk0, nk1};

  dim3 grid1(K1_GX, Bn);
  k_chunksum0<<<grid1, TPB>>>(f0);
  k_scan<<<Bn, 32>>>();
  dim3 grid3(NCH, Bn);
  k_main<<<grid3, TPB>>>(f0, out, ri, nk);
}